// round 1
// baseline (speedup 1.0000x reference)
#include <cuda_runtime.h>
#include <math.h>

#define BATCH 4
#define SEQ   2048
#define DIMS  1024
#define MTOT  (BATCH*SEQ)

// Scratch buffers (no cudaMalloc allowed) — __device__ globals.
__device__ float g_q[MTOT * DIMS];
__device__ float g_k[MTOT * DIMS];
__device__ float g_v[MTOT * DIMS];
__device__ float g_p[(size_t)BATCH * SEQ * SEQ];

#define BM 128
#define BN 128
#define BK 16
#define TM 8
#define TN 8
// threads per block = (BM/TM)*(BN/TN) = 256

// ---------------------------------------------------------------------------
// NT tile GEMM body: C[BM,BN] += A[BM,K] * B[BN,K]^T
// A row-major (lda = row stride), B row-major (ldb = row stride), both K-contiguous.
// ---------------------------------------------------------------------------
__device__ __forceinline__ void gemm_nt_body(
    const float* __restrict__ A, int lda,
    const float* __restrict__ B, int ldb,
    float* __restrict__ C, int ldc, int K)
{
    __shared__ float As[BK][BM];
    __shared__ float Bs[BK][BN];
    const int tid = threadIdx.x;
    const int ty = tid >> 4;        // 0..15
    const int tx = tid & 15;        // 0..15
    float acc[TM][TN] = {};

    for (int k0 = 0; k0 < K; k0 += BK) {
        // Load A tile (BM x BK), transpose into As[k][m]
        #pragma unroll
        for (int t = 0; t < 2; t++) {
            int idx = tid + t * 256;          // 0..511
            int r  = idx >> 2;                // row 0..127
            int c4 = (idx & 3) << 2;          // col 0,4,8,12
            float4 v = *reinterpret_cast<const float4*>(A + (size_t)r * lda + k0 + c4);
            As[c4 + 0][r] = v.x; As[c4 + 1][r] = v.y;
            As[c4 + 2][r] = v.z; As[c4 + 3][r] = v.w;
        }
        // Load B tile (BN x BK), transpose into Bs[k][n]
        #pragma unroll
        for (int t = 0; t < 2; t++) {
            int idx = tid + t * 256;
            int r  = idx >> 2;
            int c4 = (idx & 3) << 2;
            float4 v = *reinterpret_cast<const float4*>(B + (size_t)r * ldb + k0 + c4);
            Bs[c4 + 0][r] = v.x; Bs[c4 + 1][r] = v.y;
            Bs[c4 + 2][r] = v.z; Bs[c4 + 3][r] = v.w;
        }
        __syncthreads();

        #pragma unroll
        for (int k = 0; k < BK; k++) {
            float a[TM], b[TN];
            #pragma unroll
            for (int i = 0; i < TM; i++) a[i] = As[k][ty * TM + i];
            #pragma unroll
            for (int j = 0; j < TN; j++) b[j] = Bs[k][tx * TN + j];
            #pragma unroll
            for (int i = 0; i < TM; i++)
                #pragma unroll
                for (int j = 0; j < TN; j++)
                    acc[i][j] = fmaf(a[i], b[j], acc[i][j]);
        }
        __syncthreads();
    }

    #pragma unroll
    for (int i = 0; i < TM; i++) {
        float* cp = C + (size_t)(ty * TM + i) * ldc + tx * TN;
        float4 v0 = make_float4(acc[i][0], acc[i][1], acc[i][2], acc[i][3]);
        float4 v1 = make_float4(acc[i][4], acc[i][5], acc[i][6], acc[i][7]);
        *reinterpret_cast<float4*>(cp)     = v0;
        *reinterpret_cast<float4*>(cp + 4) = v1;
    }
}

// ---------------------------------------------------------------------------
// NN tile GEMM body: C[BM,BN] += A[BM,K] * B[K,BN]
// A row-major (lda), B row-major (ldb, pre-offset to tile column start).
// ---------------------------------------------------------------------------
__device__ __forceinline__ void gemm_nn_body(
    const float* __restrict__ A, int lda,
    const float* __restrict__ B, int ldb,
    float* __restrict__ C, int ldc, int K)
{
    __shared__ float As[BK][BM];
    __shared__ float Bs[BK][BN];
    const int tid = threadIdx.x;
    const int ty = tid >> 4;
    const int tx = tid & 15;
    float acc[TM][TN] = {};

    for (int k0 = 0; k0 < K; k0 += BK) {
        #pragma unroll
        for (int t = 0; t < 2; t++) {
            int idx = tid + t * 256;
            int r  = idx >> 2;
            int c4 = (idx & 3) << 2;
            float4 v = *reinterpret_cast<const float4*>(A + (size_t)r * lda + k0 + c4);
            As[c4 + 0][r] = v.x; As[c4 + 1][r] = v.y;
            As[c4 + 2][r] = v.z; As[c4 + 3][r] = v.w;
        }
        // B tile: BK rows x BN cols, N-contiguous -> direct float4 into Bs[k][n]
        #pragma unroll
        for (int t = 0; t < 2; t++) {
            int idx = tid + t * 256;          // 0..511 over 16*32 float4s
            int r  = idx >> 5;                // 0..15
            int c4 = (idx & 31) << 2;         // 0..124
            float4 v = *reinterpret_cast<const float4*>(B + (size_t)(k0 + r) * ldb + c4);
            *reinterpret_cast<float4*>(&Bs[r][c4]) = v;
        }
        __syncthreads();

        #pragma unroll
        for (int k = 0; k < BK; k++) {
            float a[TM], b[TN];
            #pragma unroll
            for (int i = 0; i < TM; i++) a[i] = As[k][ty * TM + i];
            #pragma unroll
            for (int j = 0; j < TN; j++) b[j] = Bs[k][tx * TN + j];
            #pragma unroll
            for (int i = 0; i < TM; i++)
                #pragma unroll
                for (int j = 0; j < TN; j++)
                    acc[i][j] = fmaf(a[i], b[j], acc[i][j]);
        }
        __syncthreads();
    }

    #pragma unroll
    for (int i = 0; i < TM; i++) {
        float* cp = C + (size_t)(ty * TM + i) * ldc + tx * TN;
        float4 v0 = make_float4(acc[i][0], acc[i][1], acc[i][2], acc[i][3]);
        float4 v1 = make_float4(acc[i][4], acc[i][5], acc[i][6], acc[i][7]);
        *reinterpret_cast<float4*>(cp)     = v0;
        *reinterpret_cast<float4*>(cp + 4) = v1;
    }
}

// ---------------------------------------------------------------------------
// Kernel 1: fused QKV projection.  q/k/v[m,e] = sum_d X[m,d] * W{q,k,v}[e,d]
// grid.x in [0,24): [0,8)->Wq, [8,16)->Wk, [16,24)->Wv ; grid.y = M tile.
// ---------------------------------------------------------------------------
__global__ void __launch_bounds__(256, 2)
qkv_kernel(const float* __restrict__ X, const float* __restrict__ Wq,
           const float* __restrict__ Wk, const float* __restrict__ Wv)
{
    const int bn = blockIdx.x;
    const int bm = blockIdx.y;
    const int which = bn >> 3;
    const int nc = bn & 7;
    const float* W = (which == 0) ? Wq : (which == 1) ? Wk : Wv;
    float* O       = (which == 0) ? g_q : (which == 1) ? g_k : g_v;
    gemm_nt_body(X + (size_t)bm * BM * DIMS, DIMS,
                 W + (size_t)nc * BN * DIMS, DIMS,
                 O + (size_t)bm * BM * DIMS + nc * BN, DIMS, DIMS);
}

// ---------------------------------------------------------------------------
// Kernel 2: scores S[b,q,k] = Q[b,q,:] . K[b,k,:]   (causal: skip kt > qt)
// ---------------------------------------------------------------------------
__global__ void __launch_bounds__(256, 2)
scores_kernel()
{
    const int kt = blockIdx.x;
    const int qt = blockIdx.y;
    const int b  = blockIdx.z;
    if (kt > qt) return;   // fully above diagonal; softmax never reads these
    const float* A = g_q + ((size_t)b * SEQ + qt * BM) * DIMS;
    const float* B = g_k + ((size_t)b * SEQ + kt * BN) * DIMS;
    float* C = g_p + (size_t)b * SEQ * SEQ + (size_t)(qt * BM) * SEQ + kt * BN;
    gemm_nt_body(A, DIMS, B, DIMS, C, SEQ, DIMS);
}

// ---------------------------------------------------------------------------
// Kernel 3: causal row softmax over g_p, in place. Writes zeros above diagonal
// so the P.V GEMM can use block-granular causality.
// ---------------------------------------------------------------------------
__global__ void __launch_bounds__(256)
softmax_kernel()
{
    const int row = blockIdx.x;          // 0..MTOT-1
    const int b = row / SEQ;
    const int i = row % SEQ;
    float* s = g_p + (size_t)b * SEQ * SEQ + (size_t)i * SEQ;
    const int len = i + 1;
    const int tid = threadIdx.x;
    __shared__ float red[8];

    // max
    float m = -INFINITY;
    for (int j = tid; j < len; j += 256) m = fmaxf(m, s[j]);
    #pragma unroll
    for (int o = 16; o > 0; o >>= 1) m = fmaxf(m, __shfl_xor_sync(0xFFFFFFFFu, m, o));
    if ((tid & 31) == 0) red[tid >> 5] = m;
    __syncthreads();
    if (tid < 8) {
        float v = red[tid];
        #pragma unroll
        for (int o = 4; o > 0; o >>= 1) v = fmaxf(v, __shfl_xor_sync(0xFFu, v, o));
        if (tid == 0) red[0] = v;
    }
    __syncthreads();
    m = red[0];
    __syncthreads();

    // sum of exp
    float sum = 0.0f;
    for (int j = tid; j < len; j += 256) sum += __expf(s[j] - m);
    #pragma unroll
    for (int o = 16; o > 0; o >>= 1) sum += __shfl_xor_sync(0xFFFFFFFFu, sum, o);
    if ((tid & 31) == 0) red[tid >> 5] = sum;
    __syncthreads();
    if (tid < 8) {
        float v = red[tid];
        #pragma unroll
        for (int o = 4; o > 0; o >>= 1) v += __shfl_xor_sync(0xFFu, v, o);
        if (tid == 0) red[0] = v;
    }
    __syncthreads();
    const float inv = 1.0f / red[0];

    for (int j = tid; j < SEQ; j += 256)
        s[j] = (j < len) ? __expf(s[j] - m) * inv : 0.0f;
}

// ---------------------------------------------------------------------------
// Kernel 4: O[b,q,e] = sum_k P[b,q,k] * V[b,k,e]  (K loop limited by causality)
// ---------------------------------------------------------------------------
__global__ void __launch_bounds__(256, 2)
av_kernel(float* __restrict__ Out)
{
    const int nt = blockIdx.x;
    const int qt = blockIdx.y;
    const int b  = blockIdx.z;
    const float* A = g_p + (size_t)b * SEQ * SEQ + (size_t)(qt * BM) * SEQ;
    const float* B = g_v + (size_t)b * SEQ * DIMS + nt * BN;
    float* C = Out + ((size_t)b * SEQ + qt * BM) * DIMS + nt * BN;
    gemm_nn_body(A, SEQ, B, DIMS, C, DIMS, (qt + 1) * BM);
}

// ---------------------------------------------------------------------------
extern "C" void kernel_launch(void* const* d_in, const int* in_sizes, int n_in,
                              void* d_out, int out_size)
{
    const float* X  = (const float*)d_in[0];
    const float* Wq = (const float*)d_in[1];
    const float* Wk = (const float*)d_in[2];
    const float* Wv = (const float*)d_in[3];
    float* O = (float*)d_out;

    qkv_kernel<<<dim3(3 * (DIMS / BN), MTOT / BM), 256>>>(X, Wq, Wk, Wv);
    scores_kernel<<<dim3(SEQ / BN, SEQ / BM, BATCH), 256>>>();
    softmax_kernel<<<dim3(MTOT), 256>>>();
    av_kernel<<<dim3(DIMS / BN, SEQ / BM, BATCH), 256>>>(O);
}

// round 4
// speedup vs baseline: 1.7063x; 1.7063x over previous
#include <cuda_runtime.h>
#include <cstdint>
#include <math.h>

#define BATCH 4
#define SEQ   2048
#define DIMS  1024
#define MTOT  (BATCH*SEQ)

// Scratch (no cudaMalloc allowed)
__device__ float g_q[MTOT * DIMS];
__device__ float g_k[MTOT * DIMS];
__device__ float g_vT[MTOT * DIMS];                 // [b][e][s]
__device__ float g_p[(size_t)BATCH * SEQ * SEQ];

#define BM 128
#define BN 128
#define BK 32
#define SROW 36                       // smem row stride in floats (conflict-free)
#define SM_BYTES (2 * 128 * SROW * 4) // 36864

// ---------------------------------------------------------------------------
// tf32 MMA helpers
// ---------------------------------------------------------------------------
__device__ __forceinline__ void mma1688(float* c,
    uint32_t a0, uint32_t a1, uint32_t a2, uint32_t a3, uint32_t b0, uint32_t b1)
{
    asm volatile(
        "mma.sync.aligned.m16n8k8.row.col.f32.tf32.tf32.f32 "
        "{%0,%1,%2,%3}, {%4,%5,%6,%7}, {%8,%9}, {%0,%1,%2,%3};"
        : "+f"(c[0]), "+f"(c[1]), "+f"(c[2]), "+f"(c[3])
        : "r"(a0), "r"(a1), "r"(a2), "r"(a3), "r"(b0), "r"(b1));
}

// hi = tf32-exact part (low 13 bits zeroed), lo = remainder
__device__ __forceinline__ void split_tf32(float a, uint32_t& hi, uint32_t& lo) {
    uint32_t h = __float_as_uint(a) & 0xFFFFE000u;
    hi = h;
    lo = __float_as_uint(a - __uint_as_float(h));
}

// ---------------------------------------------------------------------------
// NT mainloop on mma.sync: acc[2][8][4] += A[BM,K] * B[BN,K]^T  (3xTF32)
// 256 threads = 8 warps; warp grid 4(M) x 2(N); warp tile 32x64.
// ---------------------------------------------------------------------------
__device__ __forceinline__ void tf32_mma_nt(
    const float* __restrict__ A, int lda,
    const float* __restrict__ B, int ldb, int K,
    float* __restrict__ smem, float acc[2][8][4])
{
    float* As = smem;                  // [128][SROW]
    float* Bs = smem + 128 * SROW;
    const int tid = threadIdx.x;
    const int wid = tid >> 5, lane = tid & 31;
    const int wm = (wid & 3) * 32;     // warp M origin
    const int wn = (wid >> 2) * 64;    // warp N origin
    const int g = lane >> 2, t = lane & 3;

    for (int k0 = 0; k0 < K; k0 += BK) {
        #pragma unroll
        for (int i = 0; i < 4; i++) {
            int f = tid + i * 256;             // 1024 float4 per matrix
            int r = f >> 3, c = (f & 7) << 2;
            float4 va = *reinterpret_cast<const float4*>(A + (size_t)r * lda + k0 + c);
            *reinterpret_cast<float4*>(As + r * SROW + c) = va;
            float4 vb = *reinterpret_cast<const float4*>(B + (size_t)r * ldb + k0 + c);
            *reinterpret_cast<float4*>(Bs + r * SROW + c) = vb;
        }
        __syncthreads();

        #pragma unroll
        for (int ks = 0; ks < BK; ks += 8) {
            uint32_t ah[2][4], al[2][4];
            #pragma unroll
            for (int mf = 0; mf < 2; mf++) {
                const float* ap = As + (size_t)(wm + mf * 16 + g) * SROW + ks + t;
                split_tf32(ap[0],          ah[mf][0], al[mf][0]);
                split_tf32(ap[8 * SROW],   ah[mf][1], al[mf][1]);
                split_tf32(ap[4],          ah[mf][2], al[mf][2]);
                split_tf32(ap[8 * SROW + 4], ah[mf][3], al[mf][3]);
            }
            #pragma unroll
            for (int nf = 0; nf < 8; nf++) {
                const float* bp = Bs + (size_t)(wn + nf * 8 + g) * SROW + ks + t;
                uint32_t bh0, bl0, bh1, bl1;
                split_tf32(bp[0], bh0, bl0);
                split_tf32(bp[4], bh1, bl1);
                #pragma unroll
                for (int mf = 0; mf < 2; mf++) {
                    mma1688(acc[mf][nf], ah[mf][0], ah[mf][1], ah[mf][2], ah[mf][3], bh0, bh1);
                    mma1688(acc[mf][nf], ah[mf][0], ah[mf][1], ah[mf][2], ah[mf][3], bl0, bl1);
                    mma1688(acc[mf][nf], al[mf][0], al[mf][1], al[mf][2], al[mf][3], bh0, bh1);
                }
            }
        }
        __syncthreads();
    }
}

// Standard epilogue: acc -> C row-major
__device__ __forceinline__ void epi_store(const float acc[2][8][4],
                                          float* __restrict__ C, int ldc)
{
    const int wid = threadIdx.x >> 5, lane = threadIdx.x & 31;
    const int wm = (wid & 3) * 32, wn = (wid >> 2) * 64;
    const int g = lane >> 2, t = lane & 3;
    #pragma unroll
    for (int mf = 0; mf < 2; mf++) {
        #pragma unroll
        for (int nf = 0; nf < 8; nf++) {
            const float* c = acc[mf][nf];
            float* p0 = C + (size_t)(wm + mf * 16 + g) * ldc + wn + nf * 8 + 2 * t;
            float* p1 = p0 + 8 * ldc;
            p0[0] = c[0]; p0[1] = c[1];
            p1[0] = c[2]; p1[1] = c[3];
        }
    }
}

// ---------------------------------------------------------------------------
// Kernel 1: fused QKV. grid.x: [0,8)->Q, [8,16)->K, [16,24)->V (transposed out)
// ---------------------------------------------------------------------------
__global__ void __launch_bounds__(256, 2)
qkv_kernel(const float* __restrict__ X, const float* __restrict__ Wq,
           const float* __restrict__ Wk, const float* __restrict__ Wv)
{
    extern __shared__ float smem[];
    const int bn = blockIdx.x, bm = blockIdx.y;
    const int which = bn >> 3, nc = bn & 7;
    const float* W = (which == 0) ? Wq : (which == 1) ? Wk : Wv;

    float acc[2][8][4] = {};
    tf32_mma_nt(X + (size_t)bm * BM * DIMS, DIMS,
                W + (size_t)nc * BN * DIMS, DIMS, DIMS, smem, acc);

    if (which < 2) {
        float* O = which ? g_k : g_q;
        epi_store(acc, O + (size_t)bm * BM * DIMS + nc * BN, DIMS);
    } else {
        // transposed store: g_vT[b][e][s]
        const int wid = threadIdx.x >> 5, lane = threadIdx.x & 31;
        const int wm = (wid & 3) * 32, wn = (wid >> 2) * 64;
        const int g = lane >> 2, t = lane & 3;
        const int m0 = bm * BM;
        #pragma unroll
        for (int mf = 0; mf < 2; mf++) {
            #pragma unroll
            for (int nf = 0; nf < 8; nf++) {
                const float* c = acc[mf][nf];
                #pragma unroll
                for (int hh = 0; hh < 2; hh++) {
                    int m = m0 + wm + mf * 16 + g + hh * 8;
                    int b = m / SEQ, s = m % SEQ;
                    int e = nc * BN + wn + nf * 8 + 2 * t;
                    float* vp = g_vT + (size_t)b * DIMS * SEQ + (size_t)e * SEQ + s;
                    vp[0]   = c[hh * 2 + 0];
                    vp[SEQ] = c[hh * 2 + 1];
                }
            }
        }
    }
}

// ---------------------------------------------------------------------------
// Kernel 2: scores S = Q K^T (causal block skip)
// ---------------------------------------------------------------------------
__global__ void __launch_bounds__(256, 2)
scores_kernel()
{
    const int kt = blockIdx.x, qt = blockIdx.y, b = blockIdx.z;
    if (kt > qt) return;
    extern __shared__ float smem[];
    const float* A = g_q + ((size_t)b * SEQ + qt * BM) * DIMS;
    const float* B = g_k + ((size_t)b * SEQ + kt * BN) * DIMS;

    float acc[2][8][4] = {};
    tf32_mma_nt(A, DIMS, B, DIMS, DIMS, smem, acc);
    epi_store(acc, g_p + (size_t)b * SEQ * SEQ + (size_t)(qt * BM) * SEQ + kt * BN, SEQ);
}

// ---------------------------------------------------------------------------
// Kernel 3: causal row softmax, in place; zeros above diagonal.
// ---------------------------------------------------------------------------
__global__ void __launch_bounds__(256)
softmax_kernel()
{
    const int row = blockIdx.x;
    const int b = row / SEQ, i = row % SEQ;
    float* s = g_p + (size_t)b * SEQ * SEQ + (size_t)i * SEQ;
    const int len = i + 1;
    const int tid = threadIdx.x;
    __shared__ float red[8];

    float m = -INFINITY;
    for (int j = tid; j < len; j += 256) m = fmaxf(m, s[j]);
    #pragma unroll
    for (int o = 16; o > 0; o >>= 1) m = fmaxf(m, __shfl_xor_sync(0xFFFFFFFFu, m, o));
    if ((tid & 31) == 0) red[tid >> 5] = m;
    __syncthreads();
    if (tid < 8) {
        float v = red[tid];
        #pragma unroll
        for (int o = 4; o > 0; o >>= 1) v = fmaxf(v, __shfl_xor_sync(0xFFu, v, o));
        if (tid == 0) red[0] = v;
    }
    __syncthreads();
    m = red[0];
    __syncthreads();

    float sum = 0.0f;
    for (int j = tid; j < len; j += 256) sum += __expf(s[j] - m);
    #pragma unroll
    for (int o = 16; o > 0; o >>= 1) sum += __shfl_xor_sync(0xFFFFFFFFu, sum, o);
    if ((tid & 31) == 0) red[tid >> 5] = sum;
    __syncthreads();
    if (tid < 8) {
        float v = red[tid];
        #pragma unroll
        for (int o = 4; o > 0; o >>= 1) v += __shfl_xor_sync(0xFFu, v, o);
        if (tid == 0) red[0] = v;
    }
    __syncthreads();
    const float inv = 1.0f / red[0];

    for (int j = tid; j < SEQ; j += 256)
        s[j] = (j < len) ? __expf(s[j] - m) * inv : 0.0f;
}

// ---------------------------------------------------------------------------
// Kernel 4: O = P V  (B = rows of vT -> NT GEMM; K limited by causality)
// ---------------------------------------------------------------------------
__global__ void __launch_bounds__(256, 2)
av_kernel(float* __restrict__ Out)
{
    const int nt = blockIdx.x, qt = blockIdx.y, b = blockIdx.z;
    extern __shared__ float smem[];
    const float* A = g_p + (size_t)b * SEQ * SEQ + (size_t)(qt * BM) * SEQ;
    const float* B = g_vT + (size_t)b * DIMS * SEQ + (size_t)(nt * BN) * SEQ;

    float acc[2][8][4] = {};
    tf32_mma_nt(A, SEQ, B, SEQ, (qt + 1) * BM, smem, acc);
    epi_store(acc, Out + ((size_t)b * SEQ + qt * BM) * DIMS + nt * BN, DIMS);
}

// ---------------------------------------------------------------------------
extern "C" void kernel_launch(void* const* d_in, const int* in_sizes, int n_in,
                              void* d_out, int out_size)
{
    const float* X  = (const float*)d_in[0];
    const float* Wq = (const float*)d_in[1];
    const float* Wk = (const float*)d_in[2];
    const float* Wv = (const float*)d_in[3];
    float* O = (float*)d_out;

    cudaFuncSetAttribute(qkv_kernel,    cudaFuncAttributeMaxDynamicSharedMemorySize, SM_BYTES);
    cudaFuncSetAttribute(scores_kernel, cudaFuncAttributeMaxDynamicSharedMemorySize, SM_BYTES);
    cudaFuncSetAttribute(av_kernel,     cudaFuncAttributeMaxDynamicSharedMemorySize, SM_BYTES);

    qkv_kernel<<<dim3(3 * (DIMS / BN), MTOT / BM), 256, SM_BYTES>>>(X, Wq, Wk, Wv);
    scores_kernel<<<dim3(SEQ / BN, SEQ / BM, BATCH), 256, SM_BYTES>>>();
    softmax_kernel<<<dim3(MTOT), 256>>>();
    av_kernel<<<dim3(DIMS / BN, SEQ / BM, BATCH), 256, SM_BYTES>>>(O);
}

// round 5
// speedup vs baseline: 1.7682x; 1.0362x over previous
#include <cuda_runtime.h>
#include <cstdint>
#include <math.h>

#define BATCH 4
#define SEQ   2048
#define DIMS  1024
#define MTOT  (BATCH*SEQ)

// Scratch (no cudaMalloc allowed)
__device__ float g_q[MTOT * DIMS];
__device__ float g_k[MTOT * DIMS];
__device__ float g_vT[MTOT * DIMS];                 // [b][e][s]
__device__ float g_p[(size_t)BATCH * SEQ * SEQ];

#define BM 128
#define BN 128
#define BK 32
#define SROW 36                        // smem row stride in floats (conflict-free)
#define TILEF (128 * SROW)             // floats per tile (A or B), one stage
#define STAGEF (2 * TILEF)             // floats per stage (A + B)
#define SM_BYTES (2 * STAGEF * 4)      // 2 stages = 73728 bytes

// ---------------------------------------------------------------------------
// helpers
// ---------------------------------------------------------------------------
__device__ __forceinline__ void mma1688(float* c,
    uint32_t a0, uint32_t a1, uint32_t a2, uint32_t a3, uint32_t b0, uint32_t b1)
{
    asm volatile(
        "mma.sync.aligned.m16n8k8.row.col.f32.tf32.tf32.f32 "
        "{%0,%1,%2,%3}, {%4,%5,%6,%7}, {%8,%9}, {%0,%1,%2,%3};"
        : "+f"(c[0]), "+f"(c[1]), "+f"(c[2]), "+f"(c[3])
        : "r"(a0), "r"(a1), "r"(a2), "r"(a3), "r"(b0), "r"(b1));
}

__device__ __forceinline__ void split_tf32(float a, uint32_t& hi, uint32_t& lo) {
    uint32_t h = __float_as_uint(a) & 0xFFFFE000u;
    hi = h;
    lo = __float_as_uint(a - __uint_as_float(h));
}

__device__ __forceinline__ uint32_t smem_u32(const void* p) {
    uint32_t a;
    asm("{ .reg .u64 t; cvta.to.shared.u64 t, %1; cvt.u32.u64 %0, t; }"
        : "=r"(a) : "l"(p));
    return a;
}

__device__ __forceinline__ void cp16(uint32_t dst, const float* src) {
    asm volatile("cp.async.cg.shared.global [%0], [%1], 16;" :: "r"(dst), "l"(src));
}
#define CP_COMMIT()  asm volatile("cp.async.commit_group;" ::: "memory")
#define CP_WAIT(n)   asm volatile("cp.async.wait_group %0;" :: "n"(n) : "memory")

// ---------------------------------------------------------------------------
// Pipelined NT mainloop: acc[2][8][4] += A[BM,K] * B[BN,K]^T  (3xTF32)
// 8 warps; warp grid 4(M) x 2(N); warp tile 32x64. 2-stage cp.async pipeline.
// ---------------------------------------------------------------------------
__device__ __forceinline__ void tf32_mma_nt(
    const float* __restrict__ A, int lda,
    const float* __restrict__ B, int ldb, int K,
    float* __restrict__ smem, float acc[2][8][4])
{
    const int tid = threadIdx.x;
    const int wid = tid >> 5, lane = tid & 31;
    const int wm = (wid & 3) * 32;
    const int wn = (wid >> 2) * 64;
    const int g = lane >> 2, t = lane & 3;

    // per-thread load coords: rows r0+32i (i=0..3), constant column c
    const int r0 = tid >> 3;
    const int c  = (tid & 7) << 2;
    const uint32_t sb = smem_u32(smem);
    // smem byte offset of this thread's slot within a tile
    const uint32_t soff = (uint32_t)(r0 * SROW + c) * 4;

    const int nch = K / BK;

    // issue loads for chunk ck into stage s
    auto load_chunk = [&](int ck, int s) {
        const int k0 = ck * BK;
        const uint32_t sa = sb + (uint32_t)(s * STAGEF) * 4 + soff;
        const uint32_t sbb = sa + (uint32_t)TILEF * 4;
        const float* ap = A + (size_t)r0 * lda + k0 + c;
        const float* bp = B + (size_t)r0 * ldb + k0 + c;
        #pragma unroll
        for (int i = 0; i < 4; i++) {
            cp16(sa  + (uint32_t)(i * 32 * SROW * 4), ap + (size_t)(i * 32) * lda);
            cp16(sbb + (uint32_t)(i * 32 * SROW * 4), bp + (size_t)(i * 32) * ldb);
        }
        CP_COMMIT();
    };

    load_chunk(0, 0);

    for (int ck = 0; ck < nch; ck++) {
        if (ck + 1 < nch) {
            load_chunk(ck + 1, (ck + 1) & 1);
            CP_WAIT(1);
        } else {
            CP_WAIT(0);
        }
        __syncthreads();

        const float* As = smem + (ck & 1) * STAGEF;
        const float* Bs = As + TILEF;

        #pragma unroll
        for (int ks = 0; ks < BK; ks += 8) {
            uint32_t ah[2][4], al[2][4];
            #pragma unroll
            for (int mf = 0; mf < 2; mf++) {
                const float* ap = As + (size_t)(wm + mf * 16 + g) * SROW + ks + t;
                split_tf32(ap[0],            ah[mf][0], al[mf][0]);
                split_tf32(ap[8 * SROW],     ah[mf][1], al[mf][1]);
                split_tf32(ap[4],            ah[mf][2], al[mf][2]);
                split_tf32(ap[8 * SROW + 4], ah[mf][3], al[mf][3]);
            }
            #pragma unroll
            for (int nf = 0; nf < 8; nf++) {
                const float* bp = Bs + (size_t)(wn + nf * 8 + g) * SROW + ks + t;
                uint32_t bh0, bl0, bh1, bl1;
                split_tf32(bp[0], bh0, bl0);
                split_tf32(bp[4], bh1, bl1);
                #pragma unroll
                for (int mf = 0; mf < 2; mf++) {
                    mma1688(acc[mf][nf], ah[mf][0], ah[mf][1], ah[mf][2], ah[mf][3], bh0, bh1);
                    mma1688(acc[mf][nf], ah[mf][0], ah[mf][1], ah[mf][2], ah[mf][3], bl0, bl1);
                    mma1688(acc[mf][nf], al[mf][0], al[mf][1], al[mf][2], al[mf][3], bh0, bh1);
                }
            }
        }
        __syncthreads();
    }
}

// Standard epilogue: acc -> C row-major
__device__ __forceinline__ void epi_store(const float acc[2][8][4],
                                          float* __restrict__ C, int ldc)
{
    const int wid = threadIdx.x >> 5, lane = threadIdx.x & 31;
    const int wm = (wid & 3) * 32, wn = (wid >> 2) * 64;
    const int g = lane >> 2, t = lane & 3;
    #pragma unroll
    for (int mf = 0; mf < 2; mf++) {
        #pragma unroll
        for (int nf = 0; nf < 8; nf++) {
            const float* c = acc[mf][nf];
            float* p0 = C + (size_t)(wm + mf * 16 + g) * ldc + wn + nf * 8 + 2 * t;
            float* p1 = p0 + 8 * ldc;
            p0[0] = c[0]; p0[1] = c[1];
            p1[0] = c[2]; p1[1] = c[3];
        }
    }
}

// ---------------------------------------------------------------------------
// Kernel 1: fused QKV. grid.x: [0,8)->Q, [8,16)->K, [16,24)->V (transposed out)
// ---------------------------------------------------------------------------
__global__ void __launch_bounds__(256, 2)
qkv_kernel(const float* __restrict__ X, const float* __restrict__ Wq,
           const float* __restrict__ Wk, const float* __restrict__ Wv)
{
    extern __shared__ float smem[];
    const int bn = blockIdx.x, bm = blockIdx.y;
    const int which = bn >> 3, nc = bn & 7;
    const float* W = (which == 0) ? Wq : (which == 1) ? Wk : Wv;

    float acc[2][8][4] = {};
    tf32_mma_nt(X + (size_t)bm * BM * DIMS, DIMS,
                W + (size_t)nc * BN * DIMS, DIMS, DIMS, smem, acc);

    if (which < 2) {
        float* O = which ? g_k : g_q;
        epi_store(acc, O + (size_t)bm * BM * DIMS + nc * BN, DIMS);
    } else {
        // transposed store: g_vT[b][e][s]
        const int wid = threadIdx.x >> 5, lane = threadIdx.x & 31;
        const int wm = (wid & 3) * 32, wn = (wid >> 2) * 64;
        const int g = lane >> 2, t = lane & 3;
        const int m0 = bm * BM;
        #pragma unroll
        for (int mf = 0; mf < 2; mf++) {
            #pragma unroll
            for (int nf = 0; nf < 8; nf++) {
                const float* c = acc[mf][nf];
                #pragma unroll
                for (int hh = 0; hh < 2; hh++) {
                    int m = m0 + wm + mf * 16 + g + hh * 8;
                    int b = m / SEQ, s = m % SEQ;
                    int e = nc * BN + wn + nf * 8 + 2 * t;
                    float* vp = g_vT + (size_t)b * DIMS * SEQ + (size_t)e * SEQ + s;
                    vp[0]   = c[hh * 2 + 0];
                    vp[SEQ] = c[hh * 2 + 1];
                }
            }
        }
    }
}

// ---------------------------------------------------------------------------
// Kernel 2: scores S = Q K^T (causal block skip)
// ---------------------------------------------------------------------------
__global__ void __launch_bounds__(256, 2)
scores_kernel()
{
    const int kt = blockIdx.x, qt = blockIdx.y, b = blockIdx.z;
    if (kt > qt) return;
    extern __shared__ float smem[];
    const float* A = g_q + ((size_t)b * SEQ + qt * BM) * DIMS;
    const float* B = g_k + ((size_t)b * SEQ + kt * BN) * DIMS;

    float acc[2][8][4] = {};
    tf32_mma_nt(A, DIMS, B, DIMS, DIMS, smem, acc);
    epi_store(acc, g_p + (size_t)b * SEQ * SEQ + (size_t)(qt * BM) * SEQ + kt * BN, SEQ);
}

// ---------------------------------------------------------------------------
// Kernel 3: causal row softmax, in place; zeros above diagonal.
// ---------------------------------------------------------------------------
__global__ void __launch_bounds__(256)
softmax_kernel()
{
    const int row = blockIdx.x;
    const int b = row / SEQ, i = row % SEQ;
    float* s = g_p + (size_t)b * SEQ * SEQ + (size_t)i * SEQ;
    const int len = i + 1;
    const int tid = threadIdx.x;
    __shared__ float red[8];

    float m = -INFINITY;
    for (int j = tid; j < len; j += 256) m = fmaxf(m, s[j]);
    #pragma unroll
    for (int o = 16; o > 0; o >>= 1) m = fmaxf(m, __shfl_xor_sync(0xFFFFFFFFu, m, o));
    if ((tid & 31) == 0) red[tid >> 5] = m;
    __syncthreads();
    if (tid < 8) {
        float v = red[tid];
        #pragma unroll
        for (int o = 4; o > 0; o >>= 1) v = fmaxf(v, __shfl_xor_sync(0xFFu, v, o));
        if (tid == 0) red[0] = v;
    }
    __syncthreads();
    m = red[0];
    __syncthreads();

    float sum = 0.0f;
    for (int j = tid; j < len; j += 256) sum += __expf(s[j] - m);
    #pragma unroll
    for (int o = 16; o > 0; o >>= 1) sum += __shfl_xor_sync(0xFFFFFFFFu, sum, o);
    if ((tid & 31) == 0) red[tid >> 5] = sum;
    __syncthreads();
    if (tid < 8) {
        float v = red[tid];
        #pragma unroll
        for (int o = 4; o > 0; o >>= 1) v += __shfl_xor_sync(0xFFu, v, o);
        if (tid == 0) red[0] = v;
    }
    __syncthreads();
    const float inv = 1.0f / red[0];

    for (int j = tid; j < SEQ; j += 256)
        s[j] = (j < len) ? __expf(s[j] - m) * inv : 0.0f;
}

// ---------------------------------------------------------------------------
// Kernel 4: O = P V  (B = rows of vT -> NT GEMM; K limited by causality)
// ---------------------------------------------------------------------------
__global__ void __launch_bounds__(256, 2)
av_kernel(float* __restrict__ Out)
{
    const int nt = blockIdx.x, qt = blockIdx.y, b = blockIdx.z;
    extern __shared__ float smem[];
    const float* A = g_p + (size_t)b * SEQ * SEQ + (size_t)(qt * BM) * SEQ;
    const float* B = g_vT + (size_t)b * DIMS * SEQ + (size_t)(nt * BN) * SEQ;

    float acc[2][8][4] = {};
    tf32_mma_nt(A, SEQ, B, SEQ, (qt + 1) * BM, smem, acc);
    epi_store(acc, Out + ((size_t)b * SEQ + qt * BM) * DIMS + nt * BN, DIMS);
}

// ---------------------------------------------------------------------------
extern "C" void kernel_launch(void* const* d_in, const int* in_sizes, int n_in,
                              void* d_out, int out_size)
{
    const float* X  = (const float*)d_in[0];
    const float* Wq = (const float*)d_in[1];
    const float* Wk = (const float*)d_in[2];
    const float* Wv = (const float*)d_in[3];
    float* O = (float*)d_out;

    cudaFuncSetAttribute(qkv_kernel,    cudaFuncAttributeMaxDynamicSharedMemorySize, SM_BYTES);
    cudaFuncSetAttribute(scores_kernel, cudaFuncAttributeMaxDynamicSharedMemorySize, SM_BYTES);
    cudaFuncSetAttribute(av_kernel,     cudaFuncAttributeMaxDynamicSharedMemorySize, SM_BYTES);

    qkv_kernel<<<dim3(3 * (DIMS / BN), MTOT / BM), 256, SM_BYTES>>>(X, Wq, Wk, Wv);
    scores_kernel<<<dim3(SEQ / BN, SEQ / BM, BATCH), 256, SM_BYTES>>>();
    softmax_kernel<<<dim3(MTOT), 256>>>();
    av_kernel<<<dim3(DIMS / BN, SEQ / BM, BATCH), 256, SM_BYTES>>>(O);
}

// round 6
// speedup vs baseline: 3.2306x; 1.8271x over previous
#include <cuda_runtime.h>
#include <cuda_fp16.h>
#include <cstdint>
#include <math.h>

#define BATCH 4
#define SEQ   2048
#define DIMS  1024
#define MTOT  (BATCH*SEQ)
#define NX    (MTOT*DIMS)          // X elements
#define NW    (3*DIMS*DIMS)        // W elements (Wq|Wk|Wv)

// Scratch (no cudaMalloc allowed)
__device__ __half g_xh[NX],  g_xl[NX];
__device__ __half g_wh[NW],  g_wl[NW];
__device__ __half g_qh[NX],  g_ql[NX];
__device__ __half g_kh[NX],  g_kl[NX];
__device__ __half g_vTh[NX], g_vTl[NX];          // [b][e][s]
__device__ float  g_p[(size_t)BATCH * SEQ * SEQ];
__device__ __half g_ph[(size_t)BATCH * SEQ * SEQ], g_pl[(size_t)BATCH * SEQ * SEQ];

#define BM 128
#define BN 128
#define BK 32                      // halves per K chunk (64B rows)
#define TILE_B  8192               // 128 rows * 64B
#define STAGE_B (4 * TILE_B)       // Ah, Al, Bh, Bl
#define SM_BYTES (2 * STAGE_B)     // 65536

// swizzle: XOR 16B-chunk index (bits 4-5) with (row>>1)&3 (bits 7-8)
#define SW(o) ((o) ^ ((((o) >> 7) & 3u) << 4))

// ---------------------------------------------------------------------------
// PTX helpers
// ---------------------------------------------------------------------------
__device__ __forceinline__ uint32_t smem_u32(const void* p) {
    uint32_t a;
    asm("{ .reg .u64 t; cvta.to.shared.u64 t, %1; cvt.u32.u64 %0, t; }"
        : "=r"(a) : "l"(p));
    return a;
}
__device__ __forceinline__ void cp16(uint32_t dst, const void* src) {
    asm volatile("cp.async.cg.shared.global [%0], [%1], 16;" :: "r"(dst), "l"(src));
}
#define CP_COMMIT()  asm volatile("cp.async.commit_group;" ::: "memory")
#define CP_WAIT(n)   asm volatile("cp.async.wait_group %0;" :: "n"(n) : "memory")

__device__ __forceinline__ void ldmx4(uint32_t* r, uint32_t addr) {
    asm volatile("ldmatrix.sync.aligned.m8n8.x4.shared.b16 {%0,%1,%2,%3}, [%4];"
                 : "=r"(r[0]), "=r"(r[1]), "=r"(r[2]), "=r"(r[3]) : "r"(addr));
}
__device__ __forceinline__ void mma16816(float* c, const uint32_t* a,
                                         uint32_t b0, uint32_t b1) {
    asm volatile(
        "mma.sync.aligned.m16n8k16.row.col.f32.f16.f16.f32 "
        "{%0,%1,%2,%3}, {%4,%5,%6,%7}, {%8,%9}, {%0,%1,%2,%3};"
        : "+f"(c[0]), "+f"(c[1]), "+f"(c[2]), "+f"(c[3])
        : "r"(a[0]), "r"(a[1]), "r"(a[2]), "r"(a[3]), "r"(b0), "r"(b1));
}

__device__ __forceinline__ void split_h(float v, __half& hi, __half& lo) {
    hi = __float2half_rn(v);
    lo = __float2half_rn(v - __half2float(hi));
}

// ---------------------------------------------------------------------------
// f16-split NT mainloop: acc[2][8][4] += A[BM,K]*B[BN,K]^T (3 MMA products)
// 8 warps: 4(M) x 2(N); warp tile 32x64. 2-stage cp.async pipeline.
// ---------------------------------------------------------------------------
__device__ __forceinline__ void f16_mma_nt(
    const __half* __restrict__ Ah, const __half* __restrict__ Al, int lda,
    const __half* __restrict__ Bh, const __half* __restrict__ Bl, int ldb, int K,
    char* smem, float acc[2][8][4])
{
    const int tid = threadIdx.x;
    const int wid = tid >> 5, lane = tid & 31;
    const int wm = (wid & 3) * 32;
    const int wn = (wid >> 2) * 64;
    const int mat = lane >> 3, rw = lane & 7;
    const uint32_t sb = smem_u32(smem);

    // cp.async per-thread coords
    const int nch = K / BK;

    auto load_chunk = [&](int ck, int st) {
        const int k0 = ck * BK;
        const uint32_t base = sb + (uint32_t)st * STAGE_B;
        #pragma unroll
        for (int j = 0; j < 2; j++) {
            int c = tid + j * 256;          // 0..511
            int r = c >> 2, i = c & 3;
            uint32_t sw = SW((uint32_t)(r * 64 + i * 16));
            const __half* pa = Ah + (size_t)r * lda + k0 + i * 8;
            const __half* pl = Al + (size_t)r * lda + k0 + i * 8;
            const __half* pb = Bh + (size_t)r * ldb + k0 + i * 8;
            const __half* pq = Bl + (size_t)r * ldb + k0 + i * 8;
            cp16(base + 0 * TILE_B + sw, pa);
            cp16(base + 1 * TILE_B + sw, pl);
            cp16(base + 2 * TILE_B + sw, pb);
            cp16(base + 3 * TILE_B + sw, pq);
        }
        CP_COMMIT();
    };

    load_chunk(0, 0);

    for (int ck = 0; ck < nch; ck++) {
        if (ck + 1 < nch) {
            load_chunk(ck + 1, (ck + 1) & 1);
            CP_WAIT(1);
        } else {
            CP_WAIT(0);
        }
        __syncthreads();

        const uint32_t tb = sb + (uint32_t)(ck & 1) * STAGE_B;

        #pragma unroll
        for (int ks = 0; ks < BK; ks += 16) {
            uint32_t ah[2][4], al[2][4];
            #pragma unroll
            for (int mf = 0; mf < 2; mf++) {
                int row = wm + mf * 16 + (mat & 1) * 8 + rw;
                int col = ks + (mat >> 1) * 8;
                uint32_t off = SW((uint32_t)(row * 64 + col * 2));
                ldmx4(ah[mf], tb + 0 * TILE_B + off);
                ldmx4(al[mf], tb + 1 * TILE_B + off);
            }
            #pragma unroll
            for (int p = 0; p < 4; p++) {
                int row = wn + p * 16 + ((mat >> 1) & 1) * 8 + rw;
                int col = ks + (mat & 1) * 8;
                uint32_t off = SW((uint32_t)(row * 64 + col * 2));
                uint32_t bh[4], bl[4];
                ldmx4(bh, tb + 2 * TILE_B + off);
                ldmx4(bl, tb + 3 * TILE_B + off);
                #pragma unroll
                for (int q = 0; q < 2; q++) {
                    const int nf = 2 * p + q;
                    #pragma unroll
                    for (int mf = 0; mf < 2; mf++) {
                        mma16816(acc[mf][nf], ah[mf], bh[2*q], bh[2*q+1]);
                        mma16816(acc[mf][nf], ah[mf], bl[2*q], bl[2*q+1]);
                        mma16816(acc[mf][nf], al[mf], bh[2*q], bh[2*q+1]);
                    }
                }
            }
        }
        __syncthreads();
    }
}

// fp32 epilogue: acc -> C row-major
__device__ __forceinline__ void epi_store(const float acc[2][8][4],
                                          float* __restrict__ C, int ldc)
{
    const int wid = threadIdx.x >> 5, lane = threadIdx.x & 31;
    const int wm = (wid & 3) * 32, wn = (wid >> 2) * 64;
    const int g = lane >> 2, t = lane & 3;
    #pragma unroll
    for (int mf = 0; mf < 2; mf++) {
        #pragma unroll
        for (int nf = 0; nf < 8; nf++) {
            const float* c = acc[mf][nf];
            float* p0 = C + (size_t)(wm + mf * 16 + g) * ldc + wn + nf * 8 + 2 * t;
            float* p1 = p0 + 8 * ldc;
            p0[0] = c[0]; p0[1] = c[1];
            p1[0] = c[2]; p1[1] = c[3];
        }
    }
}

// split-half epilogue: acc -> (Ch, Cl) row-major half planes
__device__ __forceinline__ void epi_store_split(const float acc[2][8][4],
                                                __half* __restrict__ Ch,
                                                __half* __restrict__ Cl, int ldc)
{
    const int wid = threadIdx.x >> 5, lane = threadIdx.x & 31;
    const int wm = (wid & 3) * 32, wn = (wid >> 2) * 64;
    const int g = lane >> 2, t = lane & 3;
    #pragma unroll
    for (int mf = 0; mf < 2; mf++) {
        #pragma unroll
        for (int nf = 0; nf < 8; nf++) {
            const float* c = acc[mf][nf];
            #pragma unroll
            for (int hh = 0; hh < 2; hh++) {
                size_t o = (size_t)(wm + mf * 16 + g + hh * 8) * ldc + wn + nf * 8 + 2 * t;
                __half2 h, l;
                split_h(c[hh*2+0], h.x, l.x);
                split_h(c[hh*2+1], h.y, l.y);
                *reinterpret_cast<__half2*>(Ch + o) = h;
                *reinterpret_cast<__half2*>(Cl + o) = l;
            }
        }
    }
}

// ---------------------------------------------------------------------------
// Kernel 0: split X and W into half hi/lo planes
// ---------------------------------------------------------------------------
__global__ void __launch_bounds__(256)
split_kernel(const float* __restrict__ X, const float* __restrict__ Wq,
             const float* __restrict__ Wk, const float* __restrict__ Wv)
{
    size_t i = ((size_t)blockIdx.x * 256 + threadIdx.x) * 2;
    const float* src; __half* dh; __half* dl; size_t off;
    if (i < NX) {
        src = X + i; dh = g_xh; dl = g_xl; off = i;
    } else {
        size_t j = i - NX;
        int w = (int)(j >> 20);
        size_t e = j & ((1u << 20) - 1);
        src = (w == 0 ? Wq : w == 1 ? Wk : Wv) + e;
        dh = g_wh; dl = g_wl; off = j;
    }
    float2 v = *reinterpret_cast<const float2*>(src);
    __half2 h, l;
    split_h(v.x, h.x, l.x);
    split_h(v.y, h.y, l.y);
    *reinterpret_cast<__half2*>(dh + off) = h;
    *reinterpret_cast<__half2*>(dl + off) = l;
}

// ---------------------------------------------------------------------------
// Kernel 1: fused QKV. grid.x: [0,8)->Q, [8,16)->K, [16,24)->V (transposed out)
// ---------------------------------------------------------------------------
__global__ void __launch_bounds__(256, 2)
qkv_kernel()
{
    extern __shared__ char smem[];
    const int bn = blockIdx.x, bm = blockIdx.y;
    const int which = bn >> 3, nc = bn & 7;
    const size_t woff = (size_t)which * DIMS * DIMS + (size_t)nc * BN * DIMS;

    float acc[2][8][4] = {};
    f16_mma_nt(g_xh + (size_t)bm * BM * DIMS, g_xl + (size_t)bm * BM * DIMS, DIMS,
               g_wh + woff, g_wl + woff, DIMS, DIMS, smem, acc);

    if (which == 0) {
        epi_store_split(acc, g_qh + (size_t)bm * BM * DIMS + nc * BN,
                             g_ql + (size_t)bm * BM * DIMS + nc * BN, DIMS);
    } else if (which == 1) {
        epi_store_split(acc, g_kh + (size_t)bm * BM * DIMS + nc * BN,
                             g_kl + (size_t)bm * BM * DIMS + nc * BN, DIMS);
    } else {
        // transposed split store: g_vT*[b][e][s]
        const int wid = threadIdx.x >> 5, lane = threadIdx.x & 31;
        const int wm = (wid & 3) * 32, wn = (wid >> 2) * 64;
        const int g = lane >> 2, t = lane & 3;
        const int m0 = bm * BM;
        #pragma unroll
        for (int mf = 0; mf < 2; mf++) {
            #pragma unroll
            for (int nf = 0; nf < 8; nf++) {
                const float* c = acc[mf][nf];
                #pragma unroll
                for (int hh = 0; hh < 2; hh++) {
                    int m = m0 + wm + mf * 16 + g + hh * 8;
                    int b = m / SEQ, s = m % SEQ;
                    int e = nc * BN + wn + nf * 8 + 2 * t;
                    size_t o = (size_t)b * DIMS * SEQ + (size_t)e * SEQ + s;
                    __half h0, l0, h1, l1;
                    split_h(c[hh*2+0], h0, l0);
                    split_h(c[hh*2+1], h1, l1);
                    g_vTh[o] = h0;       g_vTl[o] = l0;
                    g_vTh[o + SEQ] = h1; g_vTl[o + SEQ] = l1;
                }
            }
        }
    }
}

// ---------------------------------------------------------------------------
// Kernel 2: scores S = Q K^T (causal block skip), fp32 out
// ---------------------------------------------------------------------------
__global__ void __launch_bounds__(256, 2)
scores_kernel()
{
    const int kt = blockIdx.x, qt = blockIdx.y, b = blockIdx.z;
    if (kt > qt) return;
    extern __shared__ char smem[];
    const size_t ao = ((size_t)b * SEQ + qt * BM) * DIMS;
    const size_t bo = ((size_t)b * SEQ + kt * BN) * DIMS;

    float acc[2][8][4] = {};
    f16_mma_nt(g_qh + ao, g_ql + ao, DIMS, g_kh + bo, g_kl + bo, DIMS, DIMS, smem, acc);
    epi_store(acc, g_p + (size_t)b * SEQ * SEQ + (size_t)(qt * BM) * SEQ + kt * BN, SEQ);
}

// ---------------------------------------------------------------------------
// Kernel 3: causal row softmax; emits split-half P (zeros above diagonal)
// ---------------------------------------------------------------------------
__global__ void __launch_bounds__(256)
softmax_kernel()
{
    const int row = blockIdx.x;
    const int b = row / SEQ, i = row % SEQ;
    const size_t ro = (size_t)b * SEQ * SEQ + (size_t)i * SEQ;
    const float* s = g_p + ro;
    const int len = i + 1;
    const int tid = threadIdx.x;
    __shared__ float red[8];

    float m = -INFINITY;
    for (int j = tid; j < len; j += 256) m = fmaxf(m, s[j]);
    #pragma unroll
    for (int o = 16; o > 0; o >>= 1) m = fmaxf(m, __shfl_xor_sync(0xFFFFFFFFu, m, o));
    if ((tid & 31) == 0) red[tid >> 5] = m;
    __syncthreads();
    if (tid < 8) {
        float v = red[tid];
        #pragma unroll
        for (int o = 4; o > 0; o >>= 1) v = fmaxf(v, __shfl_xor_sync(0xFFu, v, o));
        if (tid == 0) red[0] = v;
    }
    __syncthreads();
    m = red[0];
    __syncthreads();

    float sum = 0.0f;
    for (int j = tid; j < len; j += 256) sum += __expf(s[j] - m);
    #pragma unroll
    for (int o = 16; o > 0; o >>= 1) sum += __shfl_xor_sync(0xFFFFFFFFu, sum, o);
    if ((tid & 31) == 0) red[tid >> 5] = sum;
    __syncthreads();
    if (tid < 8) {
        float v = red[tid];
        #pragma unroll
        for (int o = 4; o > 0; o >>= 1) v += __shfl_xor_sync(0xFFu, v, o);
        if (tid == 0) red[0] = v;
    }
    __syncthreads();
    const float inv = 1.0f / red[0];

    for (int j = tid; j < SEQ; j += 256) {
        float p = (j < len) ? __expf(s[j] - m) * inv : 0.0f;
        __half h, l;
        split_h(p, h, l);
        g_ph[ro + j] = h;
        g_pl[ro + j] = l;
    }
}

// ---------------------------------------------------------------------------
// Kernel 4: O = P V  (NT via transposed V; K limited by causality)
// ---------------------------------------------------------------------------
__global__ void __launch_bounds__(256, 2)
av_kernel(float* __restrict__ Out)
{
    const int nt = blockIdx.x, qt = blockIdx.y, b = blockIdx.z;
    extern __shared__ char smem[];
    const size_t ao = (size_t)b * SEQ * SEQ + (size_t)(qt * BM) * SEQ;
    const size_t bo = (size_t)b * DIMS * SEQ + (size_t)(nt * BN) * SEQ;

    float acc[2][8][4] = {};
    f16_mma_nt(g_ph + ao, g_pl + ao, SEQ, g_vTh + bo, g_vTl + bo, SEQ,
               (qt + 1) * BM, smem, acc);
    epi_store(acc, Out + ((size_t)b * SEQ + qt * BM) * DIMS + nt * BN, DIMS);
}

// ---------------------------------------------------------------------------
extern "C" void kernel_launch(void* const* d_in, const int* in_sizes, int n_in,
                              void* d_out, int out_size)
{
    const float* X  = (const float*)d_in[0];
    const float* Wq = (const float*)d_in[1];
    const float* Wk = (const float*)d_in[2];
    const float* Wv = (const float*)d_in[3];
    float* O = (float*)d_out;

    cudaFuncSetAttribute(qkv_kernel,    cudaFuncAttributeMaxDynamicSharedMemorySize, SM_BYTES);
    cudaFuncSetAttribute(scores_kernel, cudaFuncAttributeMaxDynamicSharedMemorySize, SM_BYTES);
    cudaFuncSetAttribute(av_kernel,     cudaFuncAttributeMaxDynamicSharedMemorySize, SM_BYTES);

    split_kernel<<<(NX + NW) / 512, 256>>>(X, Wq, Wk, Wv);
    qkv_kernel<<<dim3(3 * (DIMS / BN), MTOT / BM), 256, SM_BYTES>>>();
    scores_kernel<<<dim3(SEQ / BN, SEQ / BM, BATCH), 256, SM_BYTES>>>();
    softmax_kernel<<<dim3(MTOT), 256>>>();
    av_kernel<<<dim3(DIMS / BN, SEQ / BM, BATCH), 256, SM_BYTES>>>(O);
}

// round 8
// speedup vs baseline: 3.4556x; 1.0697x over previous
#include <cuda_runtime.h>
#include <cuda_fp16.h>
#include <cstdint>
#include <math.h>

#define BATCH 4
#define SEQ   2048
#define DIMS  1024
#define MTOT  (BATCH*SEQ)
#define NX    (MTOT*DIMS)
#define NW    (3*DIMS*DIMS)

// Scratch (no cudaMalloc allowed)
__device__ __half g_xh[NX],  g_xl[NX];
__device__ __half g_wh[NW],  g_wl[NW];
__device__ __half g_qh[NX],  g_ql[NX];
__device__ __half g_kh[NX],  g_kl[NX];
__device__ __half g_vTh[NX], g_vTl[NX];          // [b][e][s]
__device__ float  g_p[(size_t)BATCH * SEQ * SEQ];
__device__ __half g_ph[(size_t)BATCH * SEQ * SEQ];

#define BM 128
#define BN 128
#define BK 32                      // halves per K chunk (64B rows)
#define TILE_B  8192u              // 128 rows * 64B
#define NSTAGE  3
#define SM_FULL (NSTAGE * 4 * TILE_B)   // 98304 (Ah,Al,Bh,Bl)
#define SM_AV   (NSTAGE * 3 * TILE_B)   // 73728 (Ah,Bh,Bl)

// swizzle: XOR 16B-chunk index (bits 4-5) with (row>>1)&3 (bits 7-8)
#define SW(o) ((o) ^ ((((o) >> 7) & 3u) << 4))

// ---------------------------------------------------------------------------
// PTX helpers
// ---------------------------------------------------------------------------
__device__ __forceinline__ uint32_t smem_u32(const void* p) {
    uint32_t a;
    asm("{ .reg .u64 t; cvta.to.shared.u64 t, %1; cvt.u32.u64 %0, t; }"
        : "=r"(a) : "l"(p));
    return a;
}
__device__ __forceinline__ void cp16(uint32_t dst, const void* src) {
    asm volatile("cp.async.cg.shared.global [%0], [%1], 16;" :: "r"(dst), "l"(src));
}
#define CP_COMMIT()  asm volatile("cp.async.commit_group;" ::: "memory")
#define CP_WAIT(n)   asm volatile("cp.async.wait_group %0;" :: "n"(n) : "memory")

__device__ __forceinline__ void ldmx4(uint32_t* r, uint32_t addr) {
    asm volatile("ldmatrix.sync.aligned.m8n8.x4.shared.b16 {%0,%1,%2,%3}, [%4];"
                 : "=r"(r[0]), "=r"(r[1]), "=r"(r[2]), "=r"(r[3]) : "r"(addr));
}
__device__ __forceinline__ void mma16816(float* c, const uint32_t* a,
                                         uint32_t b0, uint32_t b1) {
    asm volatile(
        "mma.sync.aligned.m16n8k16.row.col.f32.f16.f16.f32 "
        "{%0,%1,%2,%3}, {%4,%5,%6,%7}, {%8,%9}, {%0,%1,%2,%3};"
        : "+f"(c[0]), "+f"(c[1]), "+f"(c[2]), "+f"(c[3])
        : "r"(a[0]), "r"(a[1]), "r"(a[2]), "r"(a[3]), "r"(b0), "r"(b1));
}

__device__ __forceinline__ void split_h(float v, __half& hi, __half& lo) {
    hi = __float2half_rn(v);
    lo = __float2half_rn(v - __half2float(hi));
}

// ---------------------------------------------------------------------------
// f16-split NT mainloop (templated).
// USE_AL=true : 3 products (ah*bh + ah*bl + al*bh), tiles Ah,Al,Bh,Bl
// USE_AL=false: 2 products (ah*bh + ah*bl),          tiles Ah,Bh,Bl
// 8 warps: 4(M) x 2(N); warp tile 32x64. 3-stage cp.async pipeline, one
// __syncthreads per chunk, next-next chunk loads issued before compute.
// ---------------------------------------------------------------------------
template<bool USE_AL>
__device__ __forceinline__ void f16_mma_nt(
    const __half* __restrict__ Ah, const __half* __restrict__ Al, int lda,
    const __half* __restrict__ Bh, const __half* __restrict__ Bl, int ldb, int K,
    char* smem, float acc[2][8][4])
{
    constexpr uint32_t NT  = USE_AL ? 4u : 3u;
    constexpr uint32_t STG = NT * TILE_B;
    constexpr uint32_t TBH = (USE_AL ? 2u : 1u) * TILE_B;
    constexpr uint32_t TBL = TBH + TILE_B;

    const int tid = threadIdx.x;
    const int wid = tid >> 5, lane = tid & 31;
    const int wm = (wid & 3) * 32;
    const int wn = (wid >> 2) * 64;
    const int mat = lane >> 3, rw = lane & 7;
    const uint32_t sb = smem_u32(smem);
    const int nch = K / BK;

    auto load_chunk = [&](int ck, int st) {
        const int k0 = ck * BK;
        const uint32_t base = sb + (uint32_t)st * STG;
        #pragma unroll
        for (int j = 0; j < 2; j++) {
            int c = tid + j * 256;          // 0..511
            int r = c >> 2, i = c & 3;
            uint32_t sw = SW((uint32_t)(r * 64 + i * 16));
            cp16(base + sw, Ah + (size_t)r * lda + k0 + i * 8);
            if (USE_AL)
                cp16(base + TILE_B + sw, Al + (size_t)r * lda + k0 + i * 8);
            cp16(base + TBH + sw, Bh + (size_t)r * ldb + k0 + i * 8);
            cp16(base + TBL + sw, Bl + (size_t)r * ldb + k0 + i * 8);
        }
        CP_COMMIT();
    };

    load_chunk(0, 0);
    load_chunk(1, 1);

    int st = 0;
    for (int ck = 0; ck < nch; ck++) {
        if (ck + 1 < nch) { CP_WAIT(1); } else { CP_WAIT(0); }
        __syncthreads();

        if (ck + 2 < nch) {
            int s2 = st + 2; if (s2 >= NSTAGE) s2 -= NSTAGE;
            load_chunk(ck + 2, s2);
        }

        const uint32_t tb = sb + (uint32_t)st * STG;

        #pragma unroll
        for (int ks = 0; ks < BK; ks += 16) {
            uint32_t ah[2][4], al[2][4];
            #pragma unroll
            for (int mf = 0; mf < 2; mf++) {
                int row = wm + mf * 16 + (mat & 1) * 8 + rw;
                int col = ks + (mat >> 1) * 8;
                uint32_t off = SW((uint32_t)(row * 64 + col * 2));
                ldmx4(ah[mf], tb + off);
                if (USE_AL) ldmx4(al[mf], tb + TILE_B + off);
            }
            #pragma unroll
            for (int p = 0; p < 4; p++) {
                int row = wn + p * 16 + ((mat >> 1) & 1) * 8 + rw;
                int col = ks + (mat & 1) * 8;
                uint32_t off = SW((uint32_t)(row * 64 + col * 2));
                uint32_t bh[4], bl[4];
                ldmx4(bh, tb + TBH + off);
                ldmx4(bl, tb + TBL + off);
                #pragma unroll
                for (int q = 0; q < 2; q++) {
                    const int nf = 2 * p + q;
                    #pragma unroll
                    for (int mf = 0; mf < 2; mf++) {
                        mma16816(acc[mf][nf], ah[mf], bh[2*q], bh[2*q+1]);
                        mma16816(acc[mf][nf], ah[mf], bl[2*q], bl[2*q+1]);
                        if (USE_AL)
                            mma16816(acc[mf][nf], al[mf], bh[2*q], bh[2*q+1]);
                    }
                }
            }
        }
        if (++st >= NSTAGE) st = 0;
    }
    __syncthreads();
}

// fp32 epilogue: acc -> C row-major
__device__ __forceinline__ void epi_store(const float acc[2][8][4],
                                          float* __restrict__ C, int ldc)
{
    const int wid = threadIdx.x >> 5, lane = threadIdx.x & 31;
    const int wm = (wid & 3) * 32, wn = (wid >> 2) * 64;
    const int g = lane >> 2, t = lane & 3;
    #pragma unroll
    for (int mf = 0; mf < 2; mf++) {
        #pragma unroll
        for (int nf = 0; nf < 8; nf++) {
            const float* c = acc[mf][nf];
            float* p0 = C + (size_t)(wm + mf * 16 + g) * ldc + wn + nf * 8 + 2 * t;
            float* p1 = p0 + 8 * ldc;
            p0[0] = c[0]; p0[1] = c[1];
            p1[0] = c[2]; p1[1] = c[3];
        }
    }
}

// split-half epilogue: acc -> (Ch, Cl) row-major half planes
__device__ __forceinline__ void epi_store_split(const float acc[2][8][4],
                                                __half* __restrict__ Ch,
                                                __half* __restrict__ Cl, int ldc)
{
    const int wid = threadIdx.x >> 5, lane = threadIdx.x & 31;
    const int wm = (wid & 3) * 32, wn = (wid >> 2) * 64;
    const int g = lane >> 2, t = lane & 3;
    #pragma unroll
    for (int mf = 0; mf < 2; mf++) {
        #pragma unroll
        for (int nf = 0; nf < 8; nf++) {
            const float* c = acc[mf][nf];
            #pragma unroll
            for (int hh = 0; hh < 2; hh++) {
                size_t o = (size_t)(wm + mf * 16 + g + hh * 8) * ldc + wn + nf * 8 + 2 * t;
                __half2 h, l;
                split_h(c[hh*2+0], h.x, l.x);
                split_h(c[hh*2+1], h.y, l.y);
                *reinterpret_cast<__half2*>(Ch + o) = h;
                *reinterpret_cast<__half2*>(Cl + o) = l;
            }
        }
    }
}

// ---------------------------------------------------------------------------
// Kernel 0: split X and W into half hi/lo planes
// ---------------------------------------------------------------------------
__global__ void __launch_bounds__(256)
split_kernel(const float* __restrict__ X, const float* __restrict__ Wq,
             const float* __restrict__ Wk, const float* __restrict__ Wv)
{
    size_t i = ((size_t)blockIdx.x * 256 + threadIdx.x) * 2;
    const float* src; __half* dh; __half* dl; size_t off;
    if (i < NX) {
        src = X + i; dh = g_xh; dl = g_xl; off = i;
    } else {
        size_t j = i - NX;
        int w = (int)(j >> 20);
        size_t e = j & ((1u << 20) - 1);
        src = (w == 0 ? Wq : w == 1 ? Wk : Wv) + e;
        dh = g_wh; dl = g_wl; off = j;
    }
    float2 v = *reinterpret_cast<const float2*>(src);
    __half2 h, l;
    split_h(v.x, h.x, l.x);
    split_h(v.y, h.y, l.y);
    *reinterpret_cast<__half2*>(dh + off) = h;
    *reinterpret_cast<__half2*>(dl + off) = l;
}

// ---------------------------------------------------------------------------
// Kernel 1: fused QKV. grid.x: [0,8)->Q, [8,16)->K, [16,24)->V (transposed out)
// ---------------------------------------------------------------------------
__global__ void __launch_bounds__(256, 2)
qkv_kernel()
{
    extern __shared__ char smem[];
    const int bn = blockIdx.x, bm = blockIdx.y;
    const int which = bn >> 3, nc = bn & 7;
    const size_t woff = (size_t)which * DIMS * DIMS + (size_t)nc * BN * DIMS;

    float acc[2][8][4] = {};
    f16_mma_nt<true>(g_xh + (size_t)bm * BM * DIMS, g_xl + (size_t)bm * BM * DIMS, DIMS,
                     g_wh + woff, g_wl + woff, DIMS, DIMS, smem, acc);

    if (which == 0) {
        epi_store_split(acc, g_qh + (size_t)bm * BM * DIMS + nc * BN,
                             g_ql + (size_t)bm * BM * DIMS + nc * BN, DIMS);
    } else if (which == 1) {
        epi_store_split(acc, g_kh + (size_t)bm * BM * DIMS + nc * BN,
                             g_kl + (size_t)bm * BM * DIMS + nc * BN, DIMS);
    } else {
        // transposed split store: g_vT*[b][e][s]
        const int wid = threadIdx.x >> 5, lane = threadIdx.x & 31;
        const int wm = (wid & 3) * 32, wn = (wid >> 2) * 64;
        const int g = lane >> 2, t = lane & 3;
        const int m0 = bm * BM;
        #pragma unroll
        for (int mf = 0; mf < 2; mf++) {
            #pragma unroll
            for (int nf = 0; nf < 8; nf++) {
                const float* c = acc[mf][nf];
                #pragma unroll
                for (int hh = 0; hh < 2; hh++) {
                    int m = m0 + wm + mf * 16 + g + hh * 8;
                    int b = m / SEQ, s = m % SEQ;
                    int e = nc * BN + wn + nf * 8 + 2 * t;
                    size_t o = (size_t)b * DIMS * SEQ + (size_t)e * SEQ + s;
                    __half h0, l0, h1, l1;
                    split_h(c[hh*2+0], h0, l0);
                    split_h(c[hh*2+1], h1, l1);
                    g_vTh[o] = h0;       g_vTl[o] = l0;
                    g_vTh[o + SEQ] = h1; g_vTl[o + SEQ] = l1;
                }
            }
        }
    }
}

// ---------------------------------------------------------------------------
// Kernel 2: scores S = Q K^T (causal block skip), fp32 out
// ---------------------------------------------------------------------------
__global__ void __launch_bounds__(256, 2)
scores_kernel()
{
    const int kt = blockIdx.x, qt = blockIdx.y, b = blockIdx.z;
    if (kt > qt) return;
    extern __shared__ char smem[];
    const size_t ao = ((size_t)b * SEQ + qt * BM) * DIMS;
    const size_t bo = ((size_t)b * SEQ + kt * BN) * DIMS;

    float acc[2][8][4] = {};
    f16_mma_nt<true>(g_qh + ao, g_ql + ao, DIMS, g_kh + bo, g_kl + bo, DIMS,
                     DIMS, smem, acc);
    epi_store(acc, g_p + (size_t)b * SEQ * SEQ + (size_t)(qt * BM) * SEQ + kt * BN, SEQ);
}

// ---------------------------------------------------------------------------
// Kernel 3: causal row softmax; emits hi-half P only (zeros above diagonal)
// ---------------------------------------------------------------------------
__global__ void __launch_bounds__(256)
softmax_kernel()
{
    const int row = blockIdx.x;
    const int b = row / SEQ, i = row % SEQ;
    const size_t ro = (size_t)b * SEQ * SEQ + (size_t)i * SEQ;
    const float* s = g_p + ro;
    const int len = i + 1;
    const int tid = threadIdx.x;
    __shared__ float red[8];

    float m = -INFINITY;
    for (int j = tid; j < len; j += 256) m = fmaxf(m, s[j]);
    #pragma unroll
    for (int o = 16; o > 0; o >>= 1) m = fmaxf(m, __shfl_xor_sync(0xFFFFFFFFu, m, o));
    if ((tid & 31) == 0) red[tid >> 5] = m;
    __syncthreads();
    if (tid < 8) {
        float v = red[tid];
        #pragma unroll
        for (int o = 4; o > 0; o >>= 1) v = fmaxf(v, __shfl_xor_sync(0xFFu, v, o));
        if (tid == 0) red[0] = v;
    }
    __syncthreads();
    m = red[0];
    __syncthreads();

    float sum = 0.0f;
    for (int j = tid; j < len; j += 256) sum += __expf(s[j] - m);
    #pragma unroll
    for (int o = 16; o > 0; o >>= 1) sum += __shfl_xor_sync(0xFFFFFFFFu, sum, o);
    if ((tid & 31) == 0) red[tid >> 5] = sum;
    __syncthreads();
    if (tid < 8) {
        float v = red[tid];
        #pragma unroll
        for (int o = 4; o > 0; o >>= 1) v += __shfl_xor_sync(0xFFu, v, o);
        if (tid == 0) red[0] = v;
    }
    __syncthreads();
    const float inv = 1.0f / red[0];

    for (int j = tid; j < SEQ; j += 256) {
        float p = (j < len) ? __expf(s[j] - m) * inv : 0.0f;
        g_ph[ro + j] = __float2half_rn(p);
    }
}

// ---------------------------------------------------------------------------
// Kernel 4: O = P V  (2-product: ph*(vh+vl); K limited by causality)
// ---------------------------------------------------------------------------
__global__ void __launch_bounds__(256, 2)
av_kernel(float* __restrict__ Out)
{
    const int nt = blockIdx.x, qt = blockIdx.y, b = blockIdx.z;
    extern __shared__ char smem[];
    const size_t ao = (size_t)b * SEQ * SEQ + (size_t)(qt * BM) * SEQ;
    const size_t bo = (size_t)b * DIMS * SEQ + (size_t)(nt * BN) * SEQ;

    float acc[2][8][4] = {};
    f16_mma_nt<false>(g_ph + ao, (const __half*)nullptr, SEQ,
                      g_vTh + bo, g_vTl + bo, SEQ, (qt + 1) * BM, smem, acc);
    epi_store(acc, Out + ((size_t)b * SEQ + qt * BM) * DIMS + nt * BN, DIMS);
}

// ---------------------------------------------------------------------------
extern "C" void kernel_launch(void* const* d_in, const int* in_sizes, int n_in,
                              void* d_out, int out_size)
{
    const float* X  = (const float*)d_in[0];
    const float* Wq = (const float*)d_in[1];
    const float* Wk = (const float*)d_in[2];
    const float* Wv = (const float*)d_in[3];
    float* O = (float*)d_out;

    cudaFuncSetAttribute(qkv_kernel,    cudaFuncAttributeMaxDynamicSharedMemorySize, SM_FULL);
    cudaFuncSetAttribute(scores_kernel, cudaFuncAttributeMaxDynamicSharedMemorySize, SM_FULL);
    cudaFuncSetAttribute(av_kernel,     cudaFuncAttributeMaxDynamicSharedMemorySize, SM_AV);

    split_kernel<<<(NX + NW) / 512, 256>>>(X, Wq, Wk, Wv);
    qkv_kernel<<<dim3(3 * (DIMS / BN), MTOT / BM), 256, SM_FULL>>>();
    scores_kernel<<<dim3(SEQ / BN, SEQ / BM, BATCH), 256, SM_FULL>>>();
    softmax_kernel<<<dim3(MTOT), 256>>>();
    av_kernel<<<dim3(DIMS / BN, SEQ / BM, BATCH), 256, SM_AV>>>(O);
}

// round 9
// speedup vs baseline: 4.4170x; 1.2782x over previous
#include <cuda_runtime.h>
#include <cuda_fp16.h>
#include <cstdint>
#include <math.h>

#define BATCH 4
#define SEQ   2048
#define DIMS  1024
#define MTOT  (BATCH*SEQ)
#define NX    (MTOT*DIMS)
#define NWW   (DIMS*DIMS)

// Scratch (no cudaMalloc allowed)
__device__ __half g_xh[NX],   g_xl[NX];
__device__ __half g_wvh[NWW], g_wvl[NWW];
__device__ __half g_wqTh[NWW], g_wqTl[NWW];   // Wq^T [d][e]
__device__ __half g_wkTh[NWW], g_wkTl[NWW];   // Wk^T [d][e]
__device__ __half g_mth[NWW],  g_mtl[NWW];    // G^T = Wk^T*Wq  [d'][d]
__device__ __half g_th[NX],    g_tl[NX];      // T = X*G^T      [s][d']
__device__ __half g_vTh[NX];                  // V transposed   [b][e][s]
__device__ float  g_p[(size_t)BATCH * SEQ * SEQ];
__device__ __half g_ph[(size_t)BATCH * SEQ * SEQ];

#define BM 128
#define BN 128
#define BK 32                      // halves per K chunk (64B rows)
#define TILE_B  8192u              // 128 rows * 64B
#define NSTAGE  3
#define SM_P3 (NSTAGE * 4 * TILE_B)   // 98304
#define SM_P1 (NSTAGE * 2 * TILE_B)   // 49152

// swizzle: XOR 16B-chunk index (bits 4-5) with (row>>1)&3 (bits 7-8)
#define SW(o) ((o) ^ ((((o) >> 7) & 3u) << 4))

// ---------------------------------------------------------------------------
// PTX helpers
// ---------------------------------------------------------------------------
__device__ __forceinline__ uint32_t smem_u32(const void* p) {
    uint32_t a;
    asm("{ .reg .u64 t; cvta.to.shared.u64 t, %1; cvt.u32.u64 %0, t; }"
        : "=r"(a) : "l"(p));
    return a;
}
__device__ __forceinline__ void cp16(uint32_t dst, const void* src) {
    asm volatile("cp.async.cg.shared.global [%0], [%1], 16;" :: "r"(dst), "l"(src));
}
#define CP_COMMIT()  asm volatile("cp.async.commit_group;" ::: "memory")
#define CP_WAIT(n)   asm volatile("cp.async.wait_group %0;" :: "n"(n) : "memory")

__device__ __forceinline__ void ldmx4(uint32_t* r, uint32_t addr) {
    asm volatile("ldmatrix.sync.aligned.m8n8.x4.shared.b16 {%0,%1,%2,%3}, [%4];"
                 : "=r"(r[0]), "=r"(r[1]), "=r"(r[2]), "=r"(r[3]) : "r"(addr));
}
__device__ __forceinline__ void mma16816(float* c, const uint32_t* a,
                                         uint32_t b0, uint32_t b1) {
    asm volatile(
        "mma.sync.aligned.m16n8k16.row.col.f32.f16.f16.f32 "
        "{%0,%1,%2,%3}, {%4,%5,%6,%7}, {%8,%9}, {%0,%1,%2,%3};"
        : "+f"(c[0]), "+f"(c[1]), "+f"(c[2]), "+f"(c[3])
        : "r"(a[0]), "r"(a[1]), "r"(a[2]), "r"(a[3]), "r"(b0), "r"(b1));
}

__device__ __forceinline__ void split_h(float v, __half& hi, __half& lo) {
    hi = __float2half_rn(v);
    lo = __float2half_rn(v - __half2float(hi));
}

// ---------------------------------------------------------------------------
// f16-split NT mainloop.
// NPROD=3: ah*bh + ah*bl + al*bh   (tiles Ah,Al,Bh,Bl)
// NPROD=1: ah*bh                   (tiles Ah,Bh)
// 8 warps: 4(M) x 2(N); warp tile 32x64. 3-stage cp.async pipeline.
// ---------------------------------------------------------------------------
template<int NPROD>
__device__ __forceinline__ void f16_mma_nt(
    const __half* __restrict__ Ah, const __half* __restrict__ Al, int lda,
    const __half* __restrict__ Bh, const __half* __restrict__ Bl, int ldb, int K,
    char* smem, float acc[2][8][4])
{
    constexpr bool USE_AL = (NPROD == 3);
    constexpr bool USE_BL = (NPROD >= 2);
    constexpr uint32_t NT  = 1u + (USE_AL ? 1u : 0u) + 1u + (USE_BL ? 1u : 0u);
    constexpr uint32_t STG = NT * TILE_B;
    constexpr uint32_t TBH = (USE_AL ? 2u : 1u) * TILE_B;
    constexpr uint32_t TBL = TBH + TILE_B;

    const int tid = threadIdx.x;
    const int wid = tid >> 5, lane = tid & 31;
    const int wm = (wid & 3) * 32;
    const int wn = (wid >> 2) * 64;
    const int mat = lane >> 3, rw = lane & 7;
    const uint32_t sb = smem_u32(smem);
    const int nch = K / BK;

    auto load_chunk = [&](int ck, int st) {
        const int k0 = ck * BK;
        const uint32_t base = sb + (uint32_t)st * STG;
        #pragma unroll
        for (int j = 0; j < 2; j++) {
            int c = tid + j * 256;          // 0..511
            int r = c >> 2, i = c & 3;
            uint32_t sw = SW((uint32_t)(r * 64 + i * 16));
            cp16(base + sw, Ah + (size_t)r * lda + k0 + i * 8);
            if (USE_AL)
                cp16(base + TILE_B + sw, Al + (size_t)r * lda + k0 + i * 8);
            cp16(base + TBH + sw, Bh + (size_t)r * ldb + k0 + i * 8);
            if (USE_BL)
                cp16(base + TBL + sw, Bl + (size_t)r * ldb + k0 + i * 8);
        }
        CP_COMMIT();
    };

    load_chunk(0, 0);
    load_chunk(1, 1);

    int st = 0;
    for (int ck = 0; ck < nch; ck++) {
        if (ck + 1 < nch) { CP_WAIT(1); } else { CP_WAIT(0); }
        __syncthreads();

        if (ck + 2 < nch) {
            int s2 = st + 2; if (s2 >= NSTAGE) s2 -= NSTAGE;
            load_chunk(ck + 2, s2);
        }

        const uint32_t tb = sb + (uint32_t)st * STG;

        #pragma unroll
        for (int ks = 0; ks < BK; ks += 16) {
            uint32_t ah[2][4], al[2][4];
            #pragma unroll
            for (int mf = 0; mf < 2; mf++) {
                int row = wm + mf * 16 + (mat & 1) * 8 + rw;
                int col = ks + (mat >> 1) * 8;
                uint32_t off = SW((uint32_t)(row * 64 + col * 2));
                ldmx4(ah[mf], tb + off);
                if (USE_AL) ldmx4(al[mf], tb + TILE_B + off);
            }
            #pragma unroll
            for (int p = 0; p < 4; p++) {
                int row = wn + p * 16 + ((mat >> 1) & 1) * 8 + rw;
                int col = ks + (mat & 1) * 8;
                uint32_t off = SW((uint32_t)(row * 64 + col * 2));
                uint32_t bh[4], bl[4];
                ldmx4(bh, tb + TBH + off);
                if (USE_BL) ldmx4(bl, tb + TBL + off);
                #pragma unroll
                for (int q = 0; q < 2; q++) {
                    const int nf = 2 * p + q;
                    #pragma unroll
                    for (int mf = 0; mf < 2; mf++) {
                        mma16816(acc[mf][nf], ah[mf], bh[2*q], bh[2*q+1]);
                        if (USE_BL)
                            mma16816(acc[mf][nf], ah[mf], bl[2*q], bl[2*q+1]);
                        if (USE_AL)
                            mma16816(acc[mf][nf], al[mf], bh[2*q], bh[2*q+1]);
                    }
                }
            }
        }
        if (++st >= NSTAGE) st = 0;
    }
    __syncthreads();
}

// fp32 epilogue: acc -> C row-major
__device__ __forceinline__ void epi_store(const float acc[2][8][4],
                                          float* __restrict__ C, int ldc)
{
    const int wid = threadIdx.x >> 5, lane = threadIdx.x & 31;
    const int wm = (wid & 3) * 32, wn = (wid >> 2) * 64;
    const int g = lane >> 2, t = lane & 3;
    #pragma unroll
    for (int mf = 0; mf < 2; mf++) {
        #pragma unroll
        for (int nf = 0; nf < 8; nf++) {
            const float* c = acc[mf][nf];
            float* p0 = C + (size_t)(wm + mf * 16 + g) * ldc + wn + nf * 8 + 2 * t;
            float* p1 = p0 + 8 * ldc;
            p0[0] = c[0]; p0[1] = c[1];
            p1[0] = c[2]; p1[1] = c[3];
        }
    }
}

// split-half epilogue: acc -> (Ch, Cl) row-major half planes
__device__ __forceinline__ void epi_store_split(const float acc[2][8][4],
                                                __half* __restrict__ Ch,
                                                __half* __restrict__ Cl, int ldc)
{
    const int wid = threadIdx.x >> 5, lane = threadIdx.x & 31;
    const int wm = (wid & 3) * 32, wn = (wid >> 2) * 64;
    const int g = lane >> 2, t = lane & 3;
    #pragma unroll
    for (int mf = 0; mf < 2; mf++) {
        #pragma unroll
        for (int nf = 0; nf < 8; nf++) {
            const float* c = acc[mf][nf];
            #pragma unroll
            for (int hh = 0; hh < 2; hh++) {
                size_t o = (size_t)(wm + mf * 16 + g + hh * 8) * ldc + wn + nf * 8 + 2 * t;
                __half2 h, l;
                split_h(c[hh*2+0], h.x, l.x);
                split_h(c[hh*2+1], h.y, l.y);
                *reinterpret_cast<__half2*>(Ch + o) = h;
                *reinterpret_cast<__half2*>(Cl + o) = l;
            }
        }
    }
}

// ---------------------------------------------------------------------------
// Kernel 0a: split X and Wv into half hi/lo planes
// ---------------------------------------------------------------------------
__global__ void __launch_bounds__(256)
split_kernel(const float* __restrict__ X, const float* __restrict__ Wv)
{
    size_t i = ((size_t)blockIdx.x * 256 + threadIdx.x) * 2;
    const float* src; __half* dh; __half* dl; size_t off;
    if (i < NX) {
        src = X + i; dh = g_xh; dl = g_xl; off = i;
    } else {
        size_t j = i - NX;
        src = Wv + j; dh = g_wvh; dl = g_wvl; off = j;
    }
    float2 v = *reinterpret_cast<const float2*>(src);
    __half2 h, l;
    split_h(v.x, h.x, l.x);
    split_h(v.y, h.y, l.y);
    *reinterpret_cast<__half2*>(dh + off) = h;
    *reinterpret_cast<__half2*>(dl + off) = l;
}

// ---------------------------------------------------------------------------
// Kernel 0b: tiled transpose + split of Wq, Wk  ->  WqT/WkT half planes
// ---------------------------------------------------------------------------
__global__ void __launch_bounds__(256)
wtrans_kernel(const float* __restrict__ Wq, const float* __restrict__ Wk)
{
    __shared__ float tile[32][33];
    const float* W = blockIdx.z ? Wk : Wq;
    __half* dh = blockIdx.z ? g_wkTh : g_wqTh;
    __half* dl = blockIdx.z ? g_wkTl : g_wqTl;
    const int tx = threadIdx.x & 31, ty = threadIdx.x >> 5;   // 32 x 8
    const int d0 = blockIdx.x * 32;      // col block in W (d)
    const int e0 = blockIdx.y * 32;      // row block in W (e)

    #pragma unroll
    for (int j = ty; j < 32; j += 8)
        tile[j][tx] = W[(size_t)(e0 + j) * DIMS + d0 + tx];
    __syncthreads();

    #pragma unroll
    for (int j = ty; j < 32; j += 8) {
        // out[d0+j][e0+tx] = W[e0+tx][d0+j] = tile[tx][j]
        float v = tile[tx][j];
        __half h, l;
        split_h(v, h, l);
        size_t o = (size_t)(d0 + j) * DIMS + e0 + tx;
        dh[o] = h;
        dl[o] = l;
    }
}

// ---------------------------------------------------------------------------
// Kernel 1: G^T = Wk^T * Wq  (NT on transposed weights), split-half out
// ---------------------------------------------------------------------------
__global__ void __launch_bounds__(256, 2)
mt_kernel()
{
    extern __shared__ char smem[];
    const int bn = blockIdx.x, bm = blockIdx.y;

    float acc[2][8][4] = {};
    f16_mma_nt<3>(g_wkTh + (size_t)bm * BM * DIMS, g_wkTl + (size_t)bm * BM * DIMS, DIMS,
                  g_wqTh + (size_t)bn * BN * DIMS, g_wqTl + (size_t)bn * BN * DIMS, DIMS,
                  DIMS, smem, acc);
    epi_store_split(acc, g_mth + (size_t)bm * BM * DIMS + bn * BN,
                         g_mtl + (size_t)bm * BM * DIMS + bn * BN, DIMS);
}

// ---------------------------------------------------------------------------
// Kernel 2: T = X * G^T (split out) and V = X * Wv^T (transposed hi-only out)
// grid.x: [0,8) -> T, [8,16) -> V
// ---------------------------------------------------------------------------
__global__ void __launch_bounds__(256, 2)
tv_kernel()
{
    extern __shared__ char smem[];
    const int bn = blockIdx.x, bm = blockIdx.y;
    const int which = bn >> 3, nc = bn & 7;

    const __half* Bh = which ? g_wvh : g_mth;
    const __half* Bl = which ? g_wvl : g_mtl;

    float acc[2][8][4] = {};
    f16_mma_nt<3>(g_xh + (size_t)bm * BM * DIMS, g_xl + (size_t)bm * BM * DIMS, DIMS,
                  Bh + (size_t)nc * BN * DIMS, Bl + (size_t)nc * BN * DIMS, DIMS,
                  DIMS, smem, acc);

    if (which == 0) {
        epi_store_split(acc, g_th + (size_t)bm * BM * DIMS + nc * BN,
                             g_tl + (size_t)bm * BM * DIMS + nc * BN, DIMS);
    } else {
        // transposed hi-only store: g_vTh[b][e][s]
        const int wid = threadIdx.x >> 5, lane = threadIdx.x & 31;
        const int wm = (wid & 3) * 32, wn = (wid >> 2) * 64;
        const int g = lane >> 2, t = lane & 3;
        const int m0 = bm * BM;
        #pragma unroll
        for (int mf = 0; mf < 2; mf++) {
            #pragma unroll
            for (int nf = 0; nf < 8; nf++) {
                const float* c = acc[mf][nf];
                #pragma unroll
                for (int hh = 0; hh < 2; hh++) {
                    int m = m0 + wm + mf * 16 + g + hh * 8;
                    int b = m / SEQ, s = m % SEQ;
                    int e = nc * BN + wn + nf * 8 + 2 * t;
                    size_t o = (size_t)b * DIMS * SEQ + (size_t)e * SEQ + s;
                    g_vTh[o]       = __float2half_rn(c[hh*2+0]);
                    g_vTh[o + SEQ] = __float2half_rn(c[hh*2+1]);
                }
            }
        }
    }
}

// ---------------------------------------------------------------------------
// Kernel 3: scores S = T X^T (causal block skip), fp32 out
// ---------------------------------------------------------------------------
__global__ void __launch_bounds__(256, 2)
scores_kernel()
{
    const int kt = blockIdx.x, qt = blockIdx.y, b = blockIdx.z;
    if (kt > qt) return;
    extern __shared__ char smem[];
    const size_t ao = ((size_t)b * SEQ + qt * BM) * DIMS;
    const size_t bo = ((size_t)b * SEQ + kt * BN) * DIMS;

    float acc[2][8][4] = {};
    f16_mma_nt<3>(g_th + ao, g_tl + ao, DIMS, g_xh + bo, g_xl + bo, DIMS,
                  DIMS, smem, acc);
    epi_store(acc, g_p + (size_t)b * SEQ * SEQ + (size_t)(qt * BM) * SEQ + kt * BN, SEQ);
}

// ---------------------------------------------------------------------------
// Kernel 4: causal row softmax; emits hi-half P only (zeros above diagonal)
// ---------------------------------------------------------------------------
__global__ void __launch_bounds__(256)
softmax_kernel()
{
    const int row = blockIdx.x;
    const int b = row / SEQ, i = row % SEQ;
    const size_t ro = (size_t)b * SEQ * SEQ + (size_t)i * SEQ;
    const float* s = g_p + ro;
    const int len = i + 1;
    const int tid = threadIdx.x;
    __shared__ float red[8];

    float m = -INFINITY;
    for (int j = tid; j < len; j += 256) m = fmaxf(m, s[j]);
    #pragma unroll
    for (int o = 16; o > 0; o >>= 1) m = fmaxf(m, __shfl_xor_sync(0xFFFFFFFFu, m, o));
    if ((tid & 31) == 0) red[tid >> 5] = m;
    __syncthreads();
    if (tid < 8) {
        float v = red[tid];
        #pragma unroll
        for (int o = 4; o > 0; o >>= 1) v = fmaxf(v, __shfl_xor_sync(0xFFu, v, o));
        if (tid == 0) red[0] = v;
    }
    __syncthreads();
    m = red[0];
    __syncthreads();

    float sum = 0.0f;
    for (int j = tid; j < len; j += 256) sum += __expf(s[j] - m);
    #pragma unroll
    for (int o = 16; o > 0; o >>= 1) sum += __shfl_xor_sync(0xFFFFFFFFu, sum, o);
    if ((tid & 31) == 0) red[tid >> 5] = sum;
    __syncthreads();
    if (tid < 8) {
        float v = red[tid];
        #pragma unroll
        for (int o = 4; o > 0; o >>= 1) v += __shfl_xor_sync(0xFFu, v, o);
        if (tid == 0) red[0] = v;
    }
    __syncthreads();
    const float inv = 1.0f / red[0];

    for (int j = tid; j < SEQ; j += 256) {
        float p = (j < len) ? __expf(s[j] - m) * inv : 0.0f;
        g_ph[ro + j] = __float2half_rn(p);
    }
}

// ---------------------------------------------------------------------------
// Kernel 5: O = P V  (1 product: ph*vh; K limited by causality)
// ---------------------------------------------------------------------------
__global__ void __launch_bounds__(256, 2)
av_kernel(float* __restrict__ Out)
{
    const int nt = blockIdx.x, qt = blockIdx.y, b = blockIdx.z;
    extern __shared__ char smem[];
    const size_t ao = (size_t)b * SEQ * SEQ + (size_t)(qt * BM) * SEQ;
    const size_t bo = (size_t)b * DIMS * SEQ + (size_t)(nt * BN) * SEQ;

    float acc[2][8][4] = {};
    f16_mma_nt<1>(g_ph + ao, (const __half*)nullptr, SEQ,
                  g_vTh + bo, (const __half*)nullptr, SEQ, (qt + 1) * BM, smem, acc);
    epi_store(acc, Out + ((size_t)b * SEQ + qt * BM) * DIMS + nt * BN, DIMS);
}

// ---------------------------------------------------------------------------
extern "C" void kernel_launch(void* const* d_in, const int* in_sizes, int n_in,
                              void* d_out, int out_size)
{
    const float* X  = (const float*)d_in[0];
    const float* Wq = (const float*)d_in[1];
    const float* Wk = (const float*)d_in[2];
    const float* Wv = (const float*)d_in[3];
    float* O = (float*)d_out;

    cudaFuncSetAttribute(mt_kernel,     cudaFuncAttributeMaxDynamicSharedMemorySize, SM_P3);
    cudaFuncSetAttribute(tv_kernel,     cudaFuncAttributeMaxDynamicSharedMemorySize, SM_P3);
    cudaFuncSetAttribute(scores_kernel, cudaFuncAttributeMaxDynamicSharedMemorySize, SM_P3);
    cudaFuncSetAttribute(av_kernel,     cudaFuncAttributeMaxDynamicSharedMemorySize, SM_P1);

    split_kernel<<<(NX + NWW) / 512, 256>>>(X, Wv);
    wtrans_kernel<<<dim3(DIMS / 32, DIMS / 32, 2), 256>>>(Wq, Wk);
    mt_kernel<<<dim3(DIMS / BN, DIMS / BM), 256, SM_P3>>>();
    tv_kernel<<<dim3(2 * (DIMS / BN), MTOT / BM), 256, SM_P3>>>();
    scores_kernel<<<dim3(SEQ / BN, SEQ / BM, BATCH), 256, SM_P3>>>();
    softmax_kernel<<<dim3(MTOT), 256>>>();
    av_kernel<<<dim3(DIMS / BN, SEQ / BM, BATCH), 256, SM_P1>>>(O);
}

// round 10
// speedup vs baseline: 4.6145x; 1.0447x over previous
#include <cuda_runtime.h>
#include <cuda_fp16.h>
#include <cstdint>
#include <math.h>

#define BATCH 4
#define SEQ   2048
#define DIMS  1024
#define MTOT  (BATCH*SEQ)
#define NX    (MTOT*DIMS)
#define NWW   (DIMS*DIMS)

// Scratch (no cudaMalloc allowed)
__device__ __half g_xh[NX],   g_xl[NX];
__device__ __half g_wvh[NWW], g_wvl[NWW];
__device__ __half g_wqTh[NWW], g_wqTl[NWW];   // Wq^T [d][e]
__device__ __half g_wkTh[NWW], g_wkTl[NWW];   // Wk^T [d][e]
__device__ __half g_mth[NWW],  g_mtl[NWW];    // G^T = Wk^T*Wq  [d'][d]
__device__ __half g_th[NX],    g_tl[NX];      // T = X*G^T      [s][d']
__device__ __half g_vTh[NX];                  // V transposed   [b][e][s]
__device__ float  g_p[(size_t)BATCH * SEQ * SEQ];
__device__ __half g_ph[(size_t)BATCH * SEQ * SEQ];

#define BM 128
#define BN 128
#define BK 32                      // halves per K chunk (64B rows)
#define TILE_B  8192u              // 128 rows * 64B
#define NSTAGE  3
#define SM_P3 (NSTAGE * 4 * TILE_B)   // 98304
#define SM_P1 (NSTAGE * 2 * TILE_B)   // 49152

// swizzle: XOR 16B-chunk index (bits 4-5) with (row>>1)&3 (bits 7-8)
#define SW(o) ((o) ^ ((((o) >> 7) & 3u) << 4))

// ---------------------------------------------------------------------------
// PTX helpers
// ---------------------------------------------------------------------------
__device__ __forceinline__ uint32_t smem_u32(const void* p) {
    uint32_t a;
    asm("{ .reg .u64 t; cvta.to.shared.u64 t, %1; cvt.u32.u64 %0, t; }"
        : "=r"(a) : "l"(p));
    return a;
}
__device__ __forceinline__ void cp16(uint32_t dst, const void* src) {
    asm volatile("cp.async.cg.shared.global [%0], [%1], 16;" :: "r"(dst), "l"(src));
}
#define CP_COMMIT()  asm volatile("cp.async.commit_group;" ::: "memory")
#define CP_WAIT(n)   asm volatile("cp.async.wait_group %0;" :: "n"(n) : "memory")

__device__ __forceinline__ void ldmx4(uint32_t* r, uint32_t addr) {
    asm volatile("ldmatrix.sync.aligned.m8n8.x4.shared.b16 {%0,%1,%2,%3}, [%4];"
                 : "=r"(r[0]), "=r"(r[1]), "=r"(r[2]), "=r"(r[3]) : "r"(addr));
}
__device__ __forceinline__ void mma16816(float* c, const uint32_t* a,
                                         uint32_t b0, uint32_t b1) {
    asm volatile(
        "mma.sync.aligned.m16n8k16.row.col.f32.f16.f16.f32 "
        "{%0,%1,%2,%3}, {%4,%5,%6,%7}, {%8,%9}, {%0,%1,%2,%3};"
        : "+f"(c[0]), "+f"(c[1]), "+f"(c[2]), "+f"(c[3])
        : "r"(a[0]), "r"(a[1]), "r"(a[2]), "r"(a[3]), "r"(b0), "r"(b1));
}

__device__ __forceinline__ void split_h(float v, __half& hi, __half& lo) {
    hi = __float2half_rn(v);
    lo = __float2half_rn(v - __half2float(hi));
}

// ---------------------------------------------------------------------------
// f16-split NT mainloop.
// NPROD=3: ah*bh + ah*bl + al*bh   (tiles Ah,Al,Bh,Bl)
// NPROD=2: ah*bh + ah*bl           (tiles Ah,Bh,Bl)
// NPROD=1: ah*bh                   (tiles Ah,Bh)
// 8 warps: 4(M) x 2(N); warp tile 32x64. 3-stage cp.async pipeline.
// ---------------------------------------------------------------------------
template<int NPROD>
__device__ __forceinline__ void f16_mma_nt(
    const __half* __restrict__ Ah, const __half* __restrict__ Al, int lda,
    const __half* __restrict__ Bh, const __half* __restrict__ Bl, int ldb, int K,
    char* smem, float acc[2][8][4])
{
    constexpr bool USE_AL = (NPROD == 3);
    constexpr bool USE_BL = (NPROD >= 2);
    constexpr uint32_t NT  = 1u + (USE_AL ? 1u : 0u) + 1u + (USE_BL ? 1u : 0u);
    constexpr uint32_t STG = NT * TILE_B;
    constexpr uint32_t TBH = (USE_AL ? 2u : 1u) * TILE_B;
    constexpr uint32_t TBL = TBH + TILE_B;

    const int tid = threadIdx.x;
    const int wid = tid >> 5, lane = tid & 31;
    const int wm = (wid & 3) * 32;
    const int wn = (wid >> 2) * 64;
    const int mat = lane >> 3, rw = lane & 7;
    const uint32_t sb = smem_u32(smem);
    const int nch = K / BK;

    auto load_chunk = [&](int ck, int st) {
        const int k0 = ck * BK;
        const uint32_t base = sb + (uint32_t)st * STG;
        #pragma unroll
        for (int j = 0; j < 2; j++) {
            int c = tid + j * 256;          // 0..511
            int r = c >> 2, i = c & 3;
            uint32_t sw = SW((uint32_t)(r * 64 + i * 16));
            cp16(base + sw, Ah + (size_t)r * lda + k0 + i * 8);
            if (USE_AL)
                cp16(base + TILE_B + sw, Al + (size_t)r * lda + k0 + i * 8);
            cp16(base + TBH + sw, Bh + (size_t)r * ldb + k0 + i * 8);
            if (USE_BL)
                cp16(base + TBL + sw, Bl + (size_t)r * ldb + k0 + i * 8);
        }
        CP_COMMIT();
    };

    load_chunk(0, 0);
    load_chunk(1, 1);

    int st = 0;
    for (int ck = 0; ck < nch; ck++) {
        if (ck + 1 < nch) { CP_WAIT(1); } else { CP_WAIT(0); }
        __syncthreads();

        if (ck + 2 < nch) {
            int s2 = st + 2; if (s2 >= NSTAGE) s2 -= NSTAGE;
            load_chunk(ck + 2, s2);
        }

        const uint32_t tb = sb + (uint32_t)st * STG;

        #pragma unroll
        for (int ks = 0; ks < BK; ks += 16) {
            uint32_t ah[2][4], al[2][4];
            #pragma unroll
            for (int mf = 0; mf < 2; mf++) {
                int row = wm + mf * 16 + (mat & 1) * 8 + rw;
                int col = ks + (mat >> 1) * 8;
                uint32_t off = SW((uint32_t)(row * 64 + col * 2));
                ldmx4(ah[mf], tb + off);
                if (USE_AL) ldmx4(al[mf], tb + TILE_B + off);
            }
            #pragma unroll
            for (int p = 0; p < 4; p++) {
                int row = wn + p * 16 + ((mat >> 1) & 1) * 8 + rw;
                int col = ks + (mat & 1) * 8;
                uint32_t off = SW((uint32_t)(row * 64 + col * 2));
                uint32_t bh[4], bl[4];
                ldmx4(bh, tb + TBH + off);
                if (USE_BL) ldmx4(bl, tb + TBL + off);
                #pragma unroll
                for (int q = 0; q < 2; q++) {
                    const int nf = 2 * p + q;
                    #pragma unroll
                    for (int mf = 0; mf < 2; mf++) {
                        mma16816(acc[mf][nf], ah[mf], bh[2*q], bh[2*q+1]);
                        if (USE_BL)
                            mma16816(acc[mf][nf], ah[mf], bl[2*q], bl[2*q+1]);
                        if (USE_AL)
                            mma16816(acc[mf][nf], al[mf], bh[2*q], bh[2*q+1]);
                    }
                }
            }
        }
        if (++st >= NSTAGE) st = 0;
    }
    __syncthreads();
}

// fp32 epilogue: acc -> C row-major
__device__ __forceinline__ void epi_store(const float acc[2][8][4],
                                          float* __restrict__ C, int ldc)
{
    const int wid = threadIdx.x >> 5, lane = threadIdx.x & 31;
    const int wm = (wid & 3) * 32, wn = (wid >> 2) * 64;
    const int g = lane >> 2, t = lane & 3;
    #pragma unroll
    for (int mf = 0; mf < 2; mf++) {
        #pragma unroll
        for (int nf = 0; nf < 8; nf++) {
            const float* c = acc[mf][nf];
            float* p0 = C + (size_t)(wm + mf * 16 + g) * ldc + wn + nf * 8 + 2 * t;
            float* p1 = p0 + 8 * ldc;
            p0[0] = c[0]; p0[1] = c[1];
            p1[0] = c[2]; p1[1] = c[3];
        }
    }
}

// split-half epilogue: acc -> (Ch, Cl) row-major half planes
__device__ __forceinline__ void epi_store_split(const float acc[2][8][4],
                                                __half* __restrict__ Ch,
                                                __half* __restrict__ Cl, int ldc)
{
    const int wid = threadIdx.x >> 5, lane = threadIdx.x & 31;
    const int wm = (wid & 3) * 32, wn = (wid >> 2) * 64;
    const int g = lane >> 2, t = lane & 3;
    #pragma unroll
    for (int mf = 0; mf < 2; mf++) {
        #pragma unroll
        for (int nf = 0; nf < 8; nf++) {
            const float* c = acc[mf][nf];
            #pragma unroll
            for (int hh = 0; hh < 2; hh++) {
                size_t o = (size_t)(wm + mf * 16 + g + hh * 8) * ldc + wn + nf * 8 + 2 * t;
                __half2 h, l;
                split_h(c[hh*2+0], h.x, l.x);
                split_h(c[hh*2+1], h.y, l.y);
                *reinterpret_cast<__half2*>(Ch + o) = h;
                *reinterpret_cast<__half2*>(Cl + o) = l;
            }
        }
    }
}

// ---------------------------------------------------------------------------
// Kernel 0a: split X and Wv into half hi/lo planes
// ---------------------------------------------------------------------------
__global__ void __launch_bounds__(256)
split_kernel(const float* __restrict__ X, const float* __restrict__ Wv)
{
    size_t i = ((size_t)blockIdx.x * 256 + threadIdx.x) * 2;
    const float* src; __half* dh; __half* dl; size_t off;
    if (i < NX) {
        src = X + i; dh = g_xh; dl = g_xl; off = i;
    } else {
        size_t j = i - NX;
        src = Wv + j; dh = g_wvh; dl = g_wvl; off = j;
    }
    float2 v = *reinterpret_cast<const float2*>(src);
    __half2 h, l;
    split_h(v.x, h.x, l.x);
    split_h(v.y, h.y, l.y);
    *reinterpret_cast<__half2*>(dh + off) = h;
    *reinterpret_cast<__half2*>(dl + off) = l;
}

// ---------------------------------------------------------------------------
// Kernel 0b: tiled transpose + split of Wq, Wk  ->  WqT/WkT half planes
// ---------------------------------------------------------------------------
__global__ void __launch_bounds__(256)
wtrans_kernel(const float* __restrict__ Wq, const float* __restrict__ Wk)
{
    __shared__ float tile[32][33];
    const float* W = blockIdx.z ? Wk : Wq;
    __half* dh = blockIdx.z ? g_wkTh : g_wqTh;
    __half* dl = blockIdx.z ? g_wkTl : g_wqTl;
    const int tx = threadIdx.x & 31, ty = threadIdx.x >> 5;   // 32 x 8
    const int d0 = blockIdx.x * 32;
    const int e0 = blockIdx.y * 32;

    #pragma unroll
    for (int j = ty; j < 32; j += 8)
        tile[j][tx] = W[(size_t)(e0 + j) * DIMS + d0 + tx];
    __syncthreads();

    #pragma unroll
    for (int j = ty; j < 32; j += 8) {
        float v = tile[tx][j];
        __half h, l;
        split_h(v, h, l);
        size_t o = (size_t)(d0 + j) * DIMS + e0 + tx;
        dh[o] = h;
        dl[o] = l;
    }
}

// ---------------------------------------------------------------------------
// Kernel 1: G^T = Wk^T * Wq  (NT on transposed weights), split-half out
// ---------------------------------------------------------------------------
__global__ void __launch_bounds__(256, 2)
mt_kernel()
{
    extern __shared__ char smem[];
    const int bn = blockIdx.x, bm = blockIdx.y;

    float acc[2][8][4] = {};
    f16_mma_nt<3>(g_wkTh + (size_t)bm * BM * DIMS, g_wkTl + (size_t)bm * BM * DIMS, DIMS,
                  g_wqTh + (size_t)bn * BN * DIMS, g_wqTl + (size_t)bn * BN * DIMS, DIMS,
                  DIMS, smem, acc);
    epi_store_split(acc, g_mth + (size_t)bm * BM * DIMS + bn * BN,
                         g_mtl + (size_t)bm * BM * DIMS + bn * BN, DIMS);
}

// ---------------------------------------------------------------------------
// Kernel 2: T = X * G^T (3-prod, split out) and V = X * Wv^T (2-prod,
// transposed hi-only out via smem-staged coalesced store)
// grid.x: [0,8) -> T, [8,16) -> V
// ---------------------------------------------------------------------------
#define VS_PITCH 136   // halves per row of the staging tile (pad vs 128)

__global__ void __launch_bounds__(256, 2)
tv_kernel()
{
    extern __shared__ char smem[];
    const int bn = blockIdx.x, bm = blockIdx.y;
    const int which = bn >> 3, nc = bn & 7;

    float acc[2][8][4] = {};

    if (which == 0) {
        f16_mma_nt<3>(g_xh + (size_t)bm * BM * DIMS, g_xl + (size_t)bm * BM * DIMS, DIMS,
                      g_mth + (size_t)nc * BN * DIMS, g_mtl + (size_t)nc * BN * DIMS, DIMS,
                      DIMS, smem, acc);
        epi_store_split(acc, g_th + (size_t)bm * BM * DIMS + nc * BN,
                             g_tl + (size_t)bm * BM * DIMS + nc * BN, DIMS);
    } else {
        f16_mma_nt<2>(g_xh + (size_t)bm * BM * DIMS, g_xl + (size_t)bm * BM * DIMS, DIMS,
                      g_wvh + (size_t)nc * BN * DIMS, g_wvl + (size_t)nc * BN * DIMS, DIMS,
                      DIMS, smem, acc);

        // stage transposed tile in smem: vs[e_local][s_local], then coalesced out
        __half* vs = reinterpret_cast<__half*>(smem);
        const int wid = threadIdx.x >> 5, lane = threadIdx.x & 31;
        const int wm = (wid & 3) * 32, wn = (wid >> 2) * 64;
        const int g = lane >> 2, t = lane & 3;
        #pragma unroll
        for (int mf = 0; mf < 2; mf++) {
            #pragma unroll
            for (int nf = 0; nf < 8; nf++) {
                const float* c = acc[mf][nf];
                #pragma unroll
                for (int hh = 0; hh < 2; hh++) {
                    int s_local = wm + mf * 16 + g + hh * 8;
                    int e_local = wn + nf * 8 + 2 * t;
                    vs[(size_t)e_local * VS_PITCH + s_local]       = __float2half_rn(c[hh*2+0]);
                    vs[(size_t)(e_local + 1) * VS_PITCH + s_local] = __float2half_rn(c[hh*2+1]);
                }
            }
        }
        __syncthreads();

        const int m0 = bm * BM;
        const int b = m0 / SEQ, s0 = m0 % SEQ;
        __half* dst = g_vTh + (size_t)b * DIMS * SEQ + (size_t)(nc * BN) * SEQ + s0;
        // 128 rows x 128 halves = 2048 uint4; 8 per thread
        const int tid = threadIdx.x;
        #pragma unroll
        for (int j = 0; j < 8; j++) {
            int idx = tid + j * 256;
            int row = idx >> 4, c16 = idx & 15;
            uint4 v = *reinterpret_cast<const uint4*>(vs + (size_t)row * VS_PITCH + c16 * 8);
            *reinterpret_cast<uint4*>(dst + (size_t)row * SEQ + c16 * 8) = v;
        }
    }
}

// ---------------------------------------------------------------------------
// Kernel 3: scores S = T X^T (causal block skip), fp32 out
// ---------------------------------------------------------------------------
__global__ void __launch_bounds__(256, 2)
scores_kernel()
{
    const int kt = blockIdx.x, qt = blockIdx.y, b = blockIdx.z;
    if (kt > qt) return;
    extern __shared__ char smem[];
    const size_t ao = ((size_t)b * SEQ + qt * BM) * DIMS;
    const size_t bo = ((size_t)b * SEQ + kt * BN) * DIMS;

    float acc[2][8][4] = {};
    f16_mma_nt<3>(g_th + ao, g_tl + ao, DIMS, g_xh + bo, g_xl + bo, DIMS,
                  DIMS, smem, acc);
    epi_store(acc, g_p + (size_t)b * SEQ * SEQ + (size_t)(qt * BM) * SEQ + kt * BN, SEQ);
}

// ---------------------------------------------------------------------------
// Kernel 4: causal row softmax; emits hi-half P only (zeros above diagonal)
// ---------------------------------------------------------------------------
__global__ void __launch_bounds__(256)
softmax_kernel()
{
    const int row = blockIdx.x;
    const int b = row / SEQ, i = row % SEQ;
    const size_t ro = (size_t)b * SEQ * SEQ + (size_t)i * SEQ;
    const float* s = g_p + ro;
    const int len = i + 1;
    const int tid = threadIdx.x;
    __shared__ float red[8];

    float m = -INFINITY;
    for (int j = tid; j < len; j += 256) m = fmaxf(m, s[j]);
    #pragma unroll
    for (int o = 16; o > 0; o >>= 1) m = fmaxf(m, __shfl_xor_sync(0xFFFFFFFFu, m, o));
    if ((tid & 31) == 0) red[tid >> 5] = m;
    __syncthreads();
    if (tid < 8) {
        float v = red[tid];
        #pragma unroll
        for (int o = 4; o > 0; o >>= 1) v = fmaxf(v, __shfl_xor_sync(0xFFu, v, o));
        if (tid == 0) red[0] = v;
    }
    __syncthreads();
    m = red[0];
    __syncthreads();

    float sum = 0.0f;
    for (int j = tid; j < len; j += 256) sum += __expf(s[j] - m);
    #pragma unroll
    for (int o = 16; o > 0; o >>= 1) sum += __shfl_xor_sync(0xFFFFFFFFu, sum, o);
    if ((tid & 31) == 0) red[tid >> 5] = sum;
    __syncthreads();
    if (tid < 8) {
        float v = red[tid];
        #pragma unroll
        for (int o = 4; o > 0; o >>= 1) v += __shfl_xor_sync(0xFFu, v, o);
        if (tid == 0) red[0] = v;
    }
    __syncthreads();
    const float inv = 1.0f / red[0];

    for (int j = tid; j < SEQ; j += 256) {
        float p = (j < len) ? __expf(s[j] - m) * inv : 0.0f;
        g_ph[ro + j] = __float2half_rn(p);
    }
}

// ---------------------------------------------------------------------------
// Kernel 5: O = P V  (1 product: ph*vh; K limited by causality)
// ---------------------------------------------------------------------------
__global__ void __launch_bounds__(256, 2)
av_kernel(float* __restrict__ Out)
{
    const int nt = blockIdx.x, qt = blockIdx.y, b = blockIdx.z;
    extern __shared__ char smem[];
    const size_t ao = (size_t)b * SEQ * SEQ + (size_t)(qt * BM) * SEQ;
    const size_t bo = (size_t)b * DIMS * SEQ + (size_t)(nt * BN) * SEQ;

    float acc[2][8][4] = {};
    f16_mma_nt<1>(g_ph + ao, (const __half*)nullptr, SEQ,
                  g_vTh + bo, (const __half*)nullptr, SEQ, (qt + 1) * BM, smem, acc);
    epi_store(acc, Out + ((size_t)b * SEQ + qt * BM) * DIMS + nt * BN, DIMS);
}

// ---------------------------------------------------------------------------
extern "C" void kernel_launch(void* const* d_in, const int* in_sizes, int n_in,
                              void* d_out, int out_size)
{
    const float* X  = (const float*)d_in[0];
    const float* Wq = (const float*)d_in[1];
    const float* Wk = (const float*)d_in[2];
    const float* Wv = (const float*)d_in[3];
    float* O = (float*)d_out;

    cudaFuncSetAttribute(mt_kernel,     cudaFuncAttributeMaxDynamicSharedMemorySize, SM_P3);
    cudaFuncSetAttribute(tv_kernel,     cudaFuncAttributeMaxDynamicSharedMemorySize, SM_P3);
    cudaFuncSetAttribute(scores_kernel, cudaFuncAttributeMaxDynamicSharedMemorySize, SM_P3);
    cudaFuncSetAttribute(av_kernel,     cudaFuncAttributeMaxDynamicSharedMemorySize, SM_P1);

    split_kernel<<<(NX + NWW) / 512, 256>>>(X, Wv);
    wtrans_kernel<<<dim3(DIMS / 32, DIMS / 32, 2), 256>>>(Wq, Wk);
    mt_kernel<<<dim3(DIMS / BN, DIMS / BM), 256, SM_P3>>>();
    tv_kernel<<<dim3(2 * (DIMS / BN), MTOT / BM), 256, SM_P3>>>();
    scores_kernel<<<dim3(SEQ / BN, SEQ / BM, BATCH), 256, SM_P3>>>();
    softmax_kernel<<<dim3(MTOT), 256>>>();
    av_kernel<<<dim3(DIMS / BN, SEQ / BM, BATCH), 256, SM_P1>>>(O);
}

// round 11
// speedup vs baseline: 4.8658x; 1.0545x over previous
#include <cuda_runtime.h>
#include <cuda_fp16.h>
#include <cstdint>
#include <math.h>

#define BATCH 4
#define SEQ   2048
#define DIMS  1024
#define MTOT  (BATCH*SEQ)
#define NX    (MTOT*DIMS)
#define NWW   (DIMS*DIMS)

// Scratch (no cudaMalloc allowed)
__device__ __half g_xh[NX],   g_xl[NX];
__device__ __half g_wvh[NWW];
__device__ __half g_wqTh[NWW], g_wqTl[NWW];   // Wq^T [d][e]
__device__ __half g_wkTh[NWW], g_wkTl[NWW];   // Wk^T [d][e]
__device__ __half g_mth[NWW],  g_mtl[NWW];    // G^T = Wk^T*Wq  [d'][d]
__device__ __half g_th[NX],    g_tl[NX];      // T = X*G^T      [s][d']
__device__ __half g_vTh[NX];                  // V transposed   [b][e][s]
__device__ float  g_p[(size_t)BATCH * SEQ * SEQ];
__device__ __half g_ph[(size_t)BATCH * SEQ * SEQ];

#define BM 128
#define BN 128
#define BK 32                      // halves per K chunk (64B rows)
#define TILE_B  8192u              // 128 rows * 64B
#define NSTAGE  3
#define SM_P3 (NSTAGE * 4 * TILE_B)   // 98304
#define SM_P1 (NSTAGE * 2 * TILE_B)   // 49152

// swizzle: XOR 16B-chunk index (bits 4-5) with (row>>1)&3 (bits 7-8)
#define SW(o) ((o) ^ ((((o) >> 7) & 3u) << 4))

// ---------------------------------------------------------------------------
// PTX helpers
// ---------------------------------------------------------------------------
__device__ __forceinline__ uint32_t smem_u32(const void* p) {
    uint32_t a;
    asm("{ .reg .u64 t; cvta.to.shared.u64 t, %1; cvt.u32.u64 %0, t; }"
        : "=r"(a) : "l"(p));
    return a;
}
__device__ __forceinline__ void cp16(uint32_t dst, const void* src) {
    asm volatile("cp.async.cg.shared.global [%0], [%1], 16;" :: "r"(dst), "l"(src));
}
#define CP_COMMIT()  asm volatile("cp.async.commit_group;" ::: "memory")
#define CP_WAIT(n)   asm volatile("cp.async.wait_group %0;" :: "n"(n) : "memory")

__device__ __forceinline__ void ldmx4(uint32_t* r, uint32_t addr) {
    asm volatile("ldmatrix.sync.aligned.m8n8.x4.shared.b16 {%0,%1,%2,%3}, [%4];"
                 : "=r"(r[0]), "=r"(r[1]), "=r"(r[2]), "=r"(r[3]) : "r"(addr));
}
__device__ __forceinline__ void mma16816(float* c, const uint32_t* a,
                                         uint32_t b0, uint32_t b1) {
    asm volatile(
        "mma.sync.aligned.m16n8k16.row.col.f32.f16.f16.f32 "
        "{%0,%1,%2,%3}, {%4,%5,%6,%7}, {%8,%9}, {%0,%1,%2,%3};"
        : "+f"(c[0]), "+f"(c[1]), "+f"(c[2]), "+f"(c[3])
        : "r"(a[0]), "r"(a[1]), "r"(a[2]), "r"(a[3]), "r"(b0), "r"(b1));
}

__device__ __forceinline__ void split_h(float v, __half& hi, __half& lo) {
    hi = __float2half_rn(v);
    lo = __float2half_rn(v - __half2float(hi));
}

// ---------------------------------------------------------------------------
// f16-split NT mainloop.
// NPROD=3: ah*bh + ah*bl + al*bh   (tiles Ah,Al,Bh,Bl)
// NPROD=2: ah*bh + ah*bl           (tiles Ah,Bh,Bl)
// NPROD=1: ah*bh                   (tiles Ah,Bh)
// 8 warps: 4(M) x 2(N); warp tile 32x64. 3-stage cp.async pipeline.
// ---------------------------------------------------------------------------
template<int NPROD>
__device__ __forceinline__ void f16_mma_nt(
    const __half* __restrict__ Ah, const __half* __restrict__ Al, int lda,
    const __half* __restrict__ Bh, const __half* __restrict__ Bl, int ldb, int K,
    char* smem, float acc[2][8][4])
{
    constexpr bool USE_AL = (NPROD == 3);
    constexpr bool USE_BL = (NPROD >= 2);
    constexpr uint32_t NT  = 1u + (USE_AL ? 1u : 0u) + 1u + (USE_BL ? 1u : 0u);
    constexpr uint32_t STG = NT * TILE_B;
    constexpr uint32_t TBH = (USE_AL ? 2u : 1u) * TILE_B;
    constexpr uint32_t TBL = TBH + TILE_B;

    const int tid = threadIdx.x;
    const int wid = tid >> 5, lane = tid & 31;
    const int wm = (wid & 3) * 32;
    const int wn = (wid >> 2) * 64;
    const int mat = lane >> 3, rw = lane & 7;
    const uint32_t sb = smem_u32(smem);
    const int nch = K / BK;

    auto load_chunk = [&](int ck, int st) {
        const int k0 = ck * BK;
        const uint32_t base = sb + (uint32_t)st * STG;
        #pragma unroll
        for (int j = 0; j < 2; j++) {
            int c = tid + j * 256;          // 0..511
            int r = c >> 2, i = c & 3;
            uint32_t sw = SW((uint32_t)(r * 64 + i * 16));
            cp16(base + sw, Ah + (size_t)r * lda + k0 + i * 8);
            if (USE_AL)
                cp16(base + TILE_B + sw, Al + (size_t)r * lda + k0 + i * 8);
            cp16(base + TBH + sw, Bh + (size_t)r * ldb + k0 + i * 8);
            if (USE_BL)
                cp16(base + TBL + sw, Bl + (size_t)r * ldb + k0 + i * 8);
        }
        CP_COMMIT();
    };

    load_chunk(0, 0);
    load_chunk(1, 1);

    int st = 0;
    for (int ck = 0; ck < nch; ck++) {
        if (ck + 1 < nch) { CP_WAIT(1); } else { CP_WAIT(0); }
        __syncthreads();

        if (ck + 2 < nch) {
            int s2 = st + 2; if (s2 >= NSTAGE) s2 -= NSTAGE;
            load_chunk(ck + 2, s2);
        }

        const uint32_t tb = sb + (uint32_t)st * STG;

        #pragma unroll
        for (int ks = 0; ks < BK; ks += 16) {
            uint32_t ah[2][4], al[2][4];
            #pragma unroll
            for (int mf = 0; mf < 2; mf++) {
                int row = wm + mf * 16 + (mat & 1) * 8 + rw;
                int col = ks + (mat >> 1) * 8;
                uint32_t off = SW((uint32_t)(row * 64 + col * 2));
                ldmx4(ah[mf], tb + off);
                if (USE_AL) ldmx4(al[mf], tb + TILE_B + off);
            }
            #pragma unroll
            for (int p = 0; p < 4; p++) {
                int row = wn + p * 16 + ((mat >> 1) & 1) * 8 + rw;
                int col = ks + (mat & 1) * 8;
                uint32_t off = SW((uint32_t)(row * 64 + col * 2));
                uint32_t bh[4], bl[4];
                ldmx4(bh, tb + TBH + off);
                if (USE_BL) ldmx4(bl, tb + TBL + off);
                #pragma unroll
                for (int q = 0; q < 2; q++) {
                    const int nf = 2 * p + q;
                    #pragma unroll
                    for (int mf = 0; mf < 2; mf++) {
                        mma16816(acc[mf][nf], ah[mf], bh[2*q], bh[2*q+1]);
                        if (USE_BL)
                            mma16816(acc[mf][nf], ah[mf], bl[2*q], bl[2*q+1]);
                        if (USE_AL)
                            mma16816(acc[mf][nf], al[mf], bh[2*q], bh[2*q+1]);
                    }
                }
            }
        }
        if (++st >= NSTAGE) st = 0;
    }
    __syncthreads();
}

// fp32 epilogue: acc -> C row-major
__device__ __forceinline__ void epi_store(const float acc[2][8][4],
                                          float* __restrict__ C, int ldc)
{
    const int wid = threadIdx.x >> 5, lane = threadIdx.x & 31;
    const int wm = (wid & 3) * 32, wn = (wid >> 2) * 64;
    const int g = lane >> 2, t = lane & 3;
    #pragma unroll
    for (int mf = 0; mf < 2; mf++) {
        #pragma unroll
        for (int nf = 0; nf < 8; nf++) {
            const float* c = acc[mf][nf];
            float* p0 = C + (size_t)(wm + mf * 16 + g) * ldc + wn + nf * 8 + 2 * t;
            float* p1 = p0 + 8 * ldc;
            p0[0] = c[0]; p0[1] = c[1];
            p1[0] = c[2]; p1[1] = c[3];
        }
    }
}

// split-half epilogue: acc -> (Ch, Cl) row-major half planes
__device__ __forceinline__ void epi_store_split(const float acc[2][8][4],
                                                __half* __restrict__ Ch,
                                                __half* __restrict__ Cl, int ldc)
{
    const int wid = threadIdx.x >> 5, lane = threadIdx.x & 31;
    const int wm = (wid & 3) * 32, wn = (wid >> 2) * 64;
    const int g = lane >> 2, t = lane & 3;
    #pragma unroll
    for (int mf = 0; mf < 2; mf++) {
        #pragma unroll
        for (int nf = 0; nf < 8; nf++) {
            const float* c = acc[mf][nf];
            #pragma unroll
            for (int hh = 0; hh < 2; hh++) {
                size_t o = (size_t)(wm + mf * 16 + g + hh * 8) * ldc + wn + nf * 8 + 2 * t;
                __half2 h, l;
                split_h(c[hh*2+0], h.x, l.x);
                split_h(c[hh*2+1], h.y, l.y);
                *reinterpret_cast<__half2*>(Ch + o) = h;
                *reinterpret_cast<__half2*>(Cl + o) = l;
            }
        }
    }
}

// ---------------------------------------------------------------------------
// Kernel 0a: split X (hi/lo) and Wv (hi only)
// ---------------------------------------------------------------------------
__global__ void __launch_bounds__(256)
split_kernel(const float* __restrict__ X, const float* __restrict__ Wv)
{
    size_t i = ((size_t)blockIdx.x * 256 + threadIdx.x) * 2;
    if (i < NX) {
        float2 v = *reinterpret_cast<const float2*>(X + i);
        __half2 h, l;
        split_h(v.x, h.x, l.x);
        split_h(v.y, h.y, l.y);
        *reinterpret_cast<__half2*>(g_xh + i) = h;
        *reinterpret_cast<__half2*>(g_xl + i) = l;
    } else {
        size_t j = i - NX;
        float2 v = *reinterpret_cast<const float2*>(Wv + j);
        __half2 h;
        h.x = __float2half_rn(v.x);
        h.y = __float2half_rn(v.y);
        *reinterpret_cast<__half2*>(g_wvh + j) = h;
    }
}

// ---------------------------------------------------------------------------
// Kernel 0b: tiled transpose + split of Wq, Wk  ->  WqT/WkT half planes
// ---------------------------------------------------------------------------
__global__ void __launch_bounds__(256)
wtrans_kernel(const float* __restrict__ Wq, const float* __restrict__ Wk)
{
    __shared__ float tile[32][33];
    const float* W = blockIdx.z ? Wk : Wq;
    __half* dh = blockIdx.z ? g_wkTh : g_wqTh;
    __half* dl = blockIdx.z ? g_wkTl : g_wqTl;
    const int tx = threadIdx.x & 31, ty = threadIdx.x >> 5;   // 32 x 8
    const int d0 = blockIdx.x * 32;
    const int e0 = blockIdx.y * 32;

    #pragma unroll
    for (int j = ty; j < 32; j += 8)
        tile[j][tx] = W[(size_t)(e0 + j) * DIMS + d0 + tx];
    __syncthreads();

    #pragma unroll
    for (int j = ty; j < 32; j += 8) {
        float v = tile[tx][j];
        __half h, l;
        split_h(v, h, l);
        size_t o = (size_t)(d0 + j) * DIMS + e0 + tx;
        dh[o] = h;
        dl[o] = l;
    }
}

// ---------------------------------------------------------------------------
// Kernel 1: G^T = Wk^T * Wq  (NT on transposed weights), split-half out
// ---------------------------------------------------------------------------
__global__ void __launch_bounds__(256, 2)
mt_kernel()
{
    extern __shared__ char smem[];
    const int bn = blockIdx.x, bm = blockIdx.y;

    float acc[2][8][4] = {};
    f16_mma_nt<3>(g_wkTh + (size_t)bm * BM * DIMS, g_wkTl + (size_t)bm * BM * DIMS, DIMS,
                  g_wqTh + (size_t)bn * BN * DIMS, g_wqTl + (size_t)bn * BN * DIMS, DIMS,
                  DIMS, smem, acc);
    epi_store_split(acc, g_mth + (size_t)bm * BM * DIMS + bn * BN,
                         g_mtl + (size_t)bm * BM * DIMS + bn * BN, DIMS);
}

// ---------------------------------------------------------------------------
// Kernel 2: T = X * G^T (3-prod, split out) and V = X * Wv^T (1-prod,
// transposed hi-only out via smem-staged coalesced store)
// grid.x: [0,8) -> T, [8,16) -> V
// ---------------------------------------------------------------------------
#define VS_PITCH 136   // halves per row of the staging tile (pad vs 128)

__global__ void __launch_bounds__(256, 2)
tv_kernel()
{
    extern __shared__ char smem[];
    const int bn = blockIdx.x, bm = blockIdx.y;
    const int which = bn >> 3, nc = bn & 7;

    float acc[2][8][4] = {};

    if (which == 0) {
        f16_mma_nt<3>(g_xh + (size_t)bm * BM * DIMS, g_xl + (size_t)bm * BM * DIMS, DIMS,
                      g_mth + (size_t)nc * BN * DIMS, g_mtl + (size_t)nc * BN * DIMS, DIMS,
                      DIMS, smem, acc);
        epi_store_split(acc, g_th + (size_t)bm * BM * DIMS + nc * BN,
                             g_tl + (size_t)bm * BM * DIMS + nc * BN, DIMS);
    } else {
        f16_mma_nt<1>(g_xh + (size_t)bm * BM * DIMS, (const __half*)nullptr, DIMS,
                      g_wvh + (size_t)nc * BN * DIMS, (const __half*)nullptr, DIMS,
                      DIMS, smem, acc);

        // stage transposed tile in smem: vs[e_local][s_local], then coalesced out
        __half* vs = reinterpret_cast<__half*>(smem);
        const int wid = threadIdx.x >> 5, lane = threadIdx.x & 31;
        const int wm = (wid & 3) * 32, wn = (wid >> 2) * 64;
        const int g = lane >> 2, t = lane & 3;
        #pragma unroll
        for (int mf = 0; mf < 2; mf++) {
            #pragma unroll
            for (int nf = 0; nf < 8; nf++) {
                const float* c = acc[mf][nf];
                #pragma unroll
                for (int hh = 0; hh < 2; hh++) {
                    int s_local = wm + mf * 16 + g + hh * 8;
                    int e_local = wn + nf * 8 + 2 * t;
                    vs[(size_t)e_local * VS_PITCH + s_local]       = __float2half_rn(c[hh*2+0]);
                    vs[(size_t)(e_local + 1) * VS_PITCH + s_local] = __float2half_rn(c[hh*2+1]);
                }
            }
        }
        __syncthreads();

        const int m0 = bm * BM;
        const int b = m0 / SEQ, s0 = m0 % SEQ;
        __half* dst = g_vTh + (size_t)b * DIMS * SEQ + (size_t)(nc * BN) * SEQ + s0;
        const int tid = threadIdx.x;
        #pragma unroll
        for (int j = 0; j < 8; j++) {
            int idx = tid + j * 256;
            int row = idx >> 4, c16 = idx & 15;
            uint4 v = *reinterpret_cast<const uint4*>(vs + (size_t)row * VS_PITCH + c16 * 8);
            *reinterpret_cast<uint4*>(dst + (size_t)row * SEQ + c16 * 8) = v;
        }
    }
}

// ---------------------------------------------------------------------------
// Kernel 3: scores S = T X^T, lower-triangle-packed grid, fp32 out
// ---------------------------------------------------------------------------
#define NQT (SEQ / BM)                       // 16
#define NTRI (NQT * (NQT + 1) / 2)           // 136

__global__ void __launch_bounds__(256, 2)
scores_kernel()
{
    // decode lower-triangle linear index -> (qt, kt)
    int idx = blockIdx.x;
    int qt = 0;
    while ((qt + 1) * (qt + 2) / 2 <= idx) qt++;
    const int kt = idx - qt * (qt + 1) / 2;
    const int b = blockIdx.z;

    extern __shared__ char smem[];
    const size_t ao = ((size_t)b * SEQ + qt * BM) * DIMS;
    const size_t bo = ((size_t)b * SEQ + kt * BN) * DIMS;

    float acc[2][8][4] = {};
    f16_mma_nt<3>(g_th + ao, g_tl + ao, DIMS, g_xh + bo, g_xl + bo, DIMS,
                  DIMS, smem, acc);
    epi_store(acc, g_p + (size_t)b * SEQ * SEQ + (size_t)(qt * BM) * SEQ + kt * BN, SEQ);
}

// ---------------------------------------------------------------------------
// Kernel 4: causal row softmax; emits hi-half P only (zeros above diagonal)
// ---------------------------------------------------------------------------
__global__ void __launch_bounds__(256)
softmax_kernel()
{
    const int row = blockIdx.x;
    const int b = row / SEQ, i = row % SEQ;
    const size_t ro = (size_t)b * SEQ * SEQ + (size_t)i * SEQ;
    const float* s = g_p + ro;
    const int len = i + 1;
    const int tid = threadIdx.x;
    __shared__ float red[8];

    float m = -INFINITY;
    for (int j = tid; j < len; j += 256) m = fmaxf(m, s[j]);
    #pragma unroll
    for (int o = 16; o > 0; o >>= 1) m = fmaxf(m, __shfl_xor_sync(0xFFFFFFFFu, m, o));
    if ((tid & 31) == 0) red[tid >> 5] = m;
    __syncthreads();
    if (tid < 8) {
        float v = red[tid];
        #pragma unroll
        for (int o = 4; o > 0; o >>= 1) v = fmaxf(v, __shfl_xor_sync(0xFFu, v, o));
        if (tid == 0) red[0] = v;
    }
    __syncthreads();
    m = red[0];
    __syncthreads();

    float sum = 0.0f;
    for (int j = tid; j < len; j += 256) sum += __expf(s[j] - m);
    #pragma unroll
    for (int o = 16; o > 0; o >>= 1) sum += __shfl_xor_sync(0xFFFFFFFFu, sum, o);
    if ((tid & 31) == 0) red[tid >> 5] = sum;
    __syncthreads();
    if (tid < 8) {
        float v = red[tid];
        #pragma unroll
        for (int o = 4; o > 0; o >>= 1) v += __shfl_xor_sync(0xFFu, v, o);
        if (tid == 0) red[0] = v;
    }
    __syncthreads();
    const float inv = 1.0f / red[0];

    for (int j = tid; j < SEQ; j += 256) {
        float p = (j < len) ? __expf(s[j] - m) * inv : 0.0f;
        g_ph[ro + j] = __float2half_rn(p);
    }
}

// ---------------------------------------------------------------------------
// Kernel 5: O = P V  (1 product: ph*vh; K limited by causality)
// ---------------------------------------------------------------------------
__global__ void __launch_bounds__(256, 2)
av_kernel(float* __restrict__ Out)
{
    const int nt = blockIdx.x, qt = blockIdx.y, b = blockIdx.z;
    extern __shared__ char smem[];
    const size_t ao = (size_t)b * SEQ * SEQ + (size_t)(qt * BM) * SEQ;
    const size_t bo = (size_t)b * DIMS * SEQ + (size_t)(nt * BN) * SEQ;

    float acc[2][8][4] = {};
    f16_mma_nt<1>(g_ph + ao, (const __half*)nullptr, SEQ,
                  g_vTh + bo, (const __half*)nullptr, SEQ, (qt + 1) * BM, smem, acc);
    epi_store(acc, Out + ((size_t)b * SEQ + qt * BM) * DIMS + nt * BN, DIMS);
}

// ---------------------------------------------------------------------------
extern "C" void kernel_launch(void* const* d_in, const int* in_sizes, int n_in,
                              void* d_out, int out_size)
{
    const float* X  = (const float*)d_in[0];
    const float* Wq = (const float*)d_in[1];
    const float* Wk = (const float*)d_in[2];
    const float* Wv = (const float*)d_in[3];
    float* O = (float*)d_out;

    cudaFuncSetAttribute(mt_kernel,     cudaFuncAttributeMaxDynamicSharedMemorySize, SM_P3);
    cudaFuncSetAttribute(tv_kernel,     cudaFuncAttributeMaxDynamicSharedMemorySize, SM_P3);
    cudaFuncSetAttribute(scores_kernel, cudaFuncAttributeMaxDynamicSharedMemorySize, SM_P3);
    cudaFuncSetAttribute(av_kernel,     cudaFuncAttributeMaxDynamicSharedMemorySize, SM_P1);

    split_kernel<<<(NX + NWW) / 512, 256>>>(X, Wv);
    wtrans_kernel<<<dim3(DIMS / 32, DIMS / 32, 2), 256>>>(Wq, Wk);
    mt_kernel<<<dim3(DIMS / BN, DIMS / BM), 256, SM_P3>>>();
    tv_kernel<<<dim3(2 * (DIMS / BN), MTOT / BM), 256, SM_P3>>>();
    scores_kernel<<<dim3(NTRI, 1, BATCH), 256, SM_P3>>>();
    softmax_kernel<<<dim3(MTOT), 256>>>();
    av_kernel<<<dim3(DIMS / BN, SEQ / BM, BATCH), 256, SM_P1>>>(O);
}